// round 2
// baseline (speedup 1.0000x reference)
#include <cuda_runtime.h>
#include <cuda_fp16.h>
#include <math.h>

#define GS   160
#define KD   128
#define NKS  16
#define FSCALE 16384.0f
#define INV_FSCALE 6.103515625e-05f

// Field in fp16: [tensor][h][w][kd] as half2(re,im). Cell = 128 half2 = 512B.
__device__ __half2 g_field_h[3][GS][GS][KD];

struct Tw {
    float2 stw[5];
    float2 ta[5];
    float2 t5[5];
    int    k1;
};

__device__ __forceinline__ float2 cmulf(float2 a, float2 b){
    return make_float2(a.x*b.x - a.y*b.y, a.x*b.y + a.y*b.x);
}

__device__ __forceinline__ void make_tw(Tw &tw, int lane){
#pragma unroll
    for (int s = 0; s < 5; s++){
        int H = 16 >> s;
        int j = lane & (H - 1);
        float sv, cv;
        sincospif((float)j / (float)H, &sv, &cv);
        tw.stw[s] = make_float2(cv, sv);
    }
    int k1 = (int)(__brev((unsigned)lane) >> 27);
    tw.k1 = k1;
#pragma unroll
    for (int n2 = 0; n2 < 5; n2++){
        float sv, cv;
        sincospif((float)(n2 * k1) / 80.0f, &sv, &cv);
        tw.ta[n2] = make_float2(cv, sv);
    }
#pragma unroll
    for (int m = 0; m < 5; m++){
        float sv, cv;
        sincospif(0.4f * (float)m, &sv, &cv);
        tw.t5[m] = make_float2(cv, sv);
    }
}

// Inverse-sign DFT-160 across a warp: in v[j]=x[5L+j], out o[k2]=X[k1+32k2].
__device__ __forceinline__ void fft160(float2 v[5], float2 o[5], const Tw &tw, int lane){
#pragma unroll
    for (int s = 0; s < 5; s++){
        int H = 16 >> s;
        float2 t = tw.stw[s];
        bool up = (lane & H) != 0;
#pragma unroll
        for (int j = 0; j < 5; j++){
            float pr = __shfl_xor_sync(0xffffffffu, v[j].x, H);
            float pi = __shfl_xor_sync(0xffffffffu, v[j].y, H);
            float lr = v[j].x + pr;
            float li = v[j].y + pi;
            float dr = pr - v[j].x;
            float di = pi - v[j].y;
            float ur = dr * t.x - di * t.y;
            float ui = dr * t.y + di * t.x;
            v[j].x = up ? ur : lr;
            v[j].y = up ? ui : li;
        }
    }
    float2 B[5];
#pragma unroll
    for (int n2 = 0; n2 < 5; n2++) B[n2] = cmulf(v[n2], tw.ta[n2]);
#pragma unroll
    for (int k2 = 0; k2 < 5; k2++){
        float2 acc = B[0];
#pragma unroll
        for (int n2 = 1; n2 < 5; n2++){
            float2 w = tw.t5[(n2 * k2) % 5];
            acc.x += B[n2].x * w.x - B[n2].y * w.y;
            acc.y += B[n2].x * w.y + B[n2].y * w.x;
        }
        o[k2] = acc;
    }
}

// Fused 2D IFFT: one block per (kd, tensor) plane. 512 threads = 16 warps.
// smem plane: SM(a, b) = smem[a*161 + b]  (padded row 161 float2 = conflict-free-ish)
// Phase 1: FFT along axis A (a index, contiguous-in-memory axis), rows b = wid+16r.
// Phase 2: FFT along axis B in-place per SM row.
// Axis roles per tensor (A = first/phase-1, B = second/phase-2):
//   t=0 (Pu): A = z (w-axis),  B = y   -> out[y][z] = SM(z, y)
//   t=1 (Pv): A = z (w-axis),  B = x   -> out[x][z] = SM(z, x)
//   t=2 (Pw): A = y,           B = x   -> out[y][x] = SM(y, x)
#define SM(a,b) smem[(a)*161 + (b)]

__global__ void __launch_bounds__(512, 1)
spectral_kernel(const float* __restrict__ pur, const float* __restrict__ pui,
                const float* __restrict__ pvr, const float* __restrict__ pvi,
                const float* __restrict__ pwr, const float* __restrict__ pwi,
                const float* __restrict__ alpha_params)
{
    extern __shared__ float2 smem[];   // 160*161 float2 = 207488 B
    int kd  = blockIdx.x;
    int t   = blockIdx.y;
    int wid  = threadIdx.x >> 5;
    int lane = threadIdx.x & 31;

    float a0 = alpha_params[0];
    float bx = 10.0f * a0;
    float alpha = (bx > 1.0f) ? a0 : (log1pf(expf(fminf(bx, 1.0f))) * 0.1f);
    float scale = alpha * (1.0f / 25600.0f) * FSCALE;

    const float* re = (t == 0) ? pur : ((t == 1) ? pvr : pwr);
    const float* im = (t == 0) ? pui : ((t == 1) ? pvi : pwi);
    int k = kd >> 3, d = kd & 7;

    Tw tw; make_tw(tw, lane);

    // ---- phase 1: FFT over axis A, for each fixed b ----
#pragma unroll 1
    for (int r = 0; r < 10; r++){
        int b = wid + 16 * r;
        float2 v[5], o[5];
#pragma unroll
        for (int j = 0; j < 5; j++){
            int aidx = 5 * lane + j;
            int idx;
            if      (t == 0) idx = (kd * GS + b) * GS + aidx;            // (k,d, y=b, z=a)
            else if (t == 1) idx = ((k * GS + b) * 8 + d) * GS + aidx;   // (k, x=b, d, z=a)
            else             idx = ((k * GS + b) * GS + aidx) * 8 + d;   // (k, x=b, y=a, d)
            v[j] = make_float2(re[idx] * scale, im[idx] * scale);
        }
        fft160(v, o, tw, lane);
#pragma unroll
        for (int k2 = 0; k2 < 5; k2++)
            SM(tw.k1 + 32 * k2, b) = o[k2];
    }
    __syncthreads();

    // ---- phase 2: FFT over axis B, in-place per SM row ----
#pragma unroll 1
    for (int r = 0; r < 10; r++){
        int arow = wid + 16 * r;
        float2 v[5], o[5];
#pragma unroll
        for (int j = 0; j < 5; j++) v[j] = SM(arow, 5 * lane + j);
        fft160(v, o, tw, lane);
#pragma unroll
        for (int k2 = 0; k2 < 5; k2++)
            SM(arow, tw.k1 + 32 * k2) = o[k2];
    }
    __syncthreads();

    // ---- write-out: convert to fp16 half2, layout [t][h][w][kd] ----
    __half2* dst = &g_field_h[0][0][0][0];
#pragma unroll 1
    for (int idx = threadIdx.x; idx < GS * GS; idx += 512){
        int p = idx / GS;        // SM first index
        int q = idx - p * GS;    // SM second index (inner -> conflict-free LDS)
        float2 val = SM(p, q);
        // t<2: out (h=q, w=p) ; t==2: out (h=p, w=q)
        int off = (t == 2) ? (p * GS + q) : (q * GS + p);
        dst[(t * GS * GS + off) * KD + kd] = __floats2half2_rn(val.x, val.y);
    }
}

// One warp per point. Lane L owns kd = 4L..4L+3.
__global__ void sample_kernel(const float* __restrict__ xyz,
                              const float* __restrict__ boundp,
                              float* __restrict__ out, int npts)
{
    int gw   = (int)((blockIdx.x * (unsigned)blockDim.x + threadIdx.x) >> 5);
    int lane = threadIdx.x & 31;
    if (gw >= npts) return;

    float invb = 1.0f / boundp[0];
    float px = xyz[3*gw + 0] * invb;
    float py = xyz[3*gw + 1] * invb;
    float pz = xyz[3*gw + 2] * invb;

    bool hi = (lane & 1) != 0;
    float gacc = 0.0f;

    const __half2* fld = &g_field_h[0][0][0][0];

#pragma unroll
    for (int t = 0; t < 3; t++){
        float gx = (t == 2) ? px : pz;
        float gy = (t == 1) ? px : py;
        float mc = (t == 0) ? px : ((t == 1) ? py : pz);

        float ix = (gx + 1.0f) * 0.5f * 159.0f;
        float iy = (gy + 1.0f) * 0.5f * 159.0f;
        float fx = floorf(ix), fy = floorf(iy);
        float wx = ix - fx,    wy = iy - fy;
        int i0 = (int)fx, j0 = (int)fy;
        int i1 = i0 + 1,  j1 = j0 + 1;

        float vx0 = (i0 >= 0 && i0 <= 159) ? 1.0f : 0.0f;
        float vx1 = (i1 >= 0 && i1 <= 159) ? 1.0f : 0.0f;
        float vy0 = (j0 >= 0 && j0 <= 159) ? 1.0f : 0.0f;
        float vy1 = (j1 >= 0 && j1 <= 159) ? 1.0f : 0.0f;
        int i0c = max(0, min(159, i0)), i1c = max(0, min(159, i1));
        int j0c = max(0, min(159, j0)), j1c = max(0, min(159, j1));

        float w00 = (1.0f - wx) * (1.0f - wy) * vx0 * vy0;
        float w01 = wx          * (1.0f - wy) * vx1 * vy0;
        float w10 = (1.0f - wx) * wy          * vx0 * vy1;
        float w11 = wx          * wy          * vx1 * vy1;

        int base = t * GS * GS * KD + lane * 4;
        uint4 u00 = *(const uint4*)(fld + base + (j0c * GS + i0c) * KD);
        uint4 u01 = *(const uint4*)(fld + base + (j0c * GS + i1c) * KD);
        uint4 u10 = *(const uint4*)(fld + base + (j1c * GS + i0c) * KD);
        uint4 u11 = *(const uint4*)(fld + base + (j1c * GS + i1c) * KD);

        float2 R[4];
#pragma unroll
        for (int c = 0; c < 4; c++){
            unsigned a = (&u00.x)[c], b = (&u01.x)[c], e = (&u10.x)[c], f = (&u11.x)[c];
            float2 fa = __half22float2(*(__half2*)&a);
            float2 fb = __half22float2(*(__half2*)&b);
            float2 fe = __half22float2(*(__half2*)&e);
            float2 ff = __half22float2(*(__half2*)&f);
            R[c].x = w00*fa.x + w01*fb.x + w10*fe.x + w11*ff.x;
            R[c].y = w00*fa.y + w01*fb.y + w10*fe.y + w11*ff.y;
        }

        // modulation: FREQ = 0,1,2,4,8,16,32,64 via angle doubling
        float xt = (mc + 1.0f) * 0.5f;
        float s1, c1;
        sincospif(2.0f * xt, &s1, &c1);
        float cd[8], sd[8];
        cd[0] = 1.0f; sd[0] = 0.0f;
        float cc = c1, ss = s1;
        cd[1] = 2.0f * cc; sd[1] = 2.0f * ss;
#pragma unroll
        for (int j = 2; j < 8; j++){
            float nc = cc * cc - ss * ss;
            float ns = 2.0f * cc * ss;
            cc = nc; ss = ns;
            cd[j] = 2.0f * cc; sd[j] = 2.0f * ss;
        }
        float c0s = hi ? cd[4] : cd[0], s0s = hi ? sd[4] : sd[0];
        float c1s = hi ? cd[5] : cd[1], s1s = hi ? sd[5] : sd[1];
        float c2s = hi ? cd[6] : cd[2], s2s = hi ? sd[6] : sd[2];
        float c3s = hi ? cd[7] : cd[3], s3s = hi ? sd[7] : sd[3];

        gacc += R[0].x * c0s - R[0].y * s0s
              + R[1].x * c1s - R[1].y * s1s
              + R[2].x * c2s - R[2].y * s2s
              + R[3].x * c3s - R[3].y * s3s;
    }

    gacc *= INV_FSCALE;
    gacc += __shfl_xor_sync(0xffffffffu, gacc, 1);
    if ((lane & 1) == 0)
        out[gw * NKS + (lane >> 1)] = gacc;
}

extern "C" void kernel_launch(void* const* d_in, const int* in_sizes, int n_in,
                              void* d_out, int out_size)
{
    const float* xyz   = (const float*)d_in[0];
    const float* bound = (const float*)d_in[1];
    const float* alpha = (const float*)d_in[2];
    const float* pur   = (const float*)d_in[3];
    const float* pui   = (const float*)d_in[4];
    const float* pvr   = (const float*)d_in[5];
    const float* pvi   = (const float*)d_in[6];
    const float* pwr   = (const float*)d_in[7];
    const float* pwi   = (const float*)d_in[8];

    const int smem_bytes = GS * 161 * (int)sizeof(float2);  // 207488
    cudaFuncSetAttribute(spectral_kernel,
                         cudaFuncAttributeMaxDynamicSharedMemorySize, smem_bytes);

    dim3 gs(KD, 3);
    spectral_kernel<<<gs, 512, smem_bytes>>>(pur, pui, pvr, pvi, pwr, pwi, alpha);

    int npts = in_sizes[0] / 3;
    int nblocks = (npts * 32 + 255) / 256;
    sample_kernel<<<nblocks, 256>>>(xyz, bound, (float*)d_out, npts);
}

// round 3
// speedup vs baseline: 1.6697x; 1.6697x over previous
#include <cuda_runtime.h>
#include <cuda_fp16.h>
#include <math.h>

#define GS   160
#define KD   128
#define NKS  16
#define FSCALE      262144.0f            // 2^18
#define INV_FSCALE  3.814697265625e-06f  // 2^-18

// Intermediates / field in fp16 (values pre-scaled by FSCALE).
__device__ __half2 g_tmp_h[3][KD][GS][GS];     // [t][kd][w_k][h]
__device__ __half2 g_field_h[3][GS][GS][KD];   // [t][h][w][kd]

struct Tw {
    float2 stw[5];
    float2 ta[5];
    float2 t5[5];
    int    k1;
};

__device__ __forceinline__ float2 cmulf(float2 a, float2 b){
    return make_float2(a.x*b.x - a.y*b.y, a.x*b.y + a.y*b.x);
}

__device__ __forceinline__ void make_tw(Tw &tw, int lane){
#pragma unroll
    for (int s = 0; s < 5; s++){
        int H = 16 >> s;
        int j = lane & (H - 1);
        float sv, cv;
        sincospif((float)j / (float)H, &sv, &cv);
        tw.stw[s] = make_float2(cv, sv);
    }
    int k1 = (int)(__brev((unsigned)lane) >> 27);
    tw.k1 = k1;
#pragma unroll
    for (int n2 = 0; n2 < 5; n2++){
        float sv, cv;
        sincospif((float)(n2 * k1) / 80.0f, &sv, &cv);
        tw.ta[n2] = make_float2(cv, sv);
    }
#pragma unroll
    for (int m = 0; m < 5; m++){
        float sv, cv;
        sincospif(0.4f * (float)m, &sv, &cv);
        tw.t5[m] = make_float2(cv, sv);
    }
}

// Inverse-sign DFT-160 across a warp: in v[j]=x[5L+j], out o[k2]=X[k1+32k2].
__device__ __forceinline__ void fft160(float2 v[5], float2 o[5], const Tw &tw, int lane){
#pragma unroll
    for (int s = 0; s < 5; s++){
        int H = 16 >> s;
        float2 t = tw.stw[s];
        bool up = (lane & H) != 0;
#pragma unroll
        for (int j = 0; j < 5; j++){
            float pr = __shfl_xor_sync(0xffffffffu, v[j].x, H);
            float pi = __shfl_xor_sync(0xffffffffu, v[j].y, H);
            float lr = v[j].x + pr;
            float li = v[j].y + pi;
            float dr = pr - v[j].x;
            float di = pi - v[j].y;
            float ur = dr * t.x - di * t.y;
            float ui = dr * t.y + di * t.x;
            v[j].x = up ? ur : lr;
            v[j].y = up ? ui : li;
        }
    }
    float2 B[5];
#pragma unroll
    for (int n2 = 0; n2 < 5; n2++) B[n2] = cmulf(v[n2], tw.ta[n2]);
#pragma unroll
    for (int k2 = 0; k2 < 5; k2++){
        float2 acc = B[0];
#pragma unroll
        for (int n2 = 1; n2 < 5; n2++){
            float2 w = tw.t5[(n2 * k2) % 5];
            acc.x += B[n2].x * w.x - B[n2].y * w.y;
            acc.y += B[n2].x * w.y + B[n2].y * w.x;
        }
        o[k2] = acc;
    }
}

// Pass 1: IDFT along axis-A. grid=(10,128,3), block=128. Each warp: 4 rows.
__global__ void __launch_bounds__(128)
pass1_kernel(const float* __restrict__ pur, const float* __restrict__ pui,
             const float* __restrict__ pvr, const float* __restrict__ pvi,
             const float* __restrict__ pwr, const float* __restrict__ pwi,
             const float* __restrict__ alpha_params)
{
    int t    = blockIdx.z;
    int kd   = blockIdx.y;
    int hb   = blockIdx.x;            // 0..9, covers 16 rows
    int wid  = threadIdx.x >> 5;
    int lane = threadIdx.x & 31;

    float a0 = alpha_params[0];
    float bx = 10.0f * a0;
    float alpha = (bx > 1.0f) ? a0 : (log1pf(expf(fminf(bx, 1.0f))) * 0.1f);
    float scale = alpha * (1.0f / 25600.0f) * FSCALE;

    const float* re = (t == 0) ? pur : ((t == 1) ? pvr : pwr);
    const float* im = (t == 0) ? pui : ((t == 1) ? pvi : pwi);
    int k = kd >> 3, d = kd & 7;

    Tw tw; make_tw(tw, lane);

    __shared__ __half2 sm1[GS * 17];   // [w_k]*17 + rowlocal (pad 17: k1*17%32 distinct)

#pragma unroll 1
    for (int r = 0; r < 4; r++){
        int b = hb * 16 + wid * 4 + r;     // fixed row (h)
        float2 v[5], o[5];
#pragma unroll
        for (int j = 0; j < 5; j++){
            int a = 5 * lane + j;          // FFT axis index
            int idx;
            if      (t == 0) idx = (kd * GS + b) * GS + a;            // (k,d, y=b, z=a)
            else if (t == 1) idx = ((k * GS + b) * 8 + d) * GS + a;   // (k, x=b, d, z=a)
            else             idx = ((k * GS + a) * GS + b) * 8 + d;   // (k, x=a, y=b, d)
            v[j] = make_float2(re[idx] * scale, im[idx] * scale);
        }
        fft160(v, o, tw, lane);
#pragma unroll
        for (int k2 = 0; k2 < 5; k2++)
            sm1[(tw.k1 + 32 * k2) * 17 + (wid * 4 + r)] =
                __floats2half2_rn(o[k2].x, o[k2].y);
    }
    __syncthreads();

    // write out: g_tmp[t][kd][w_k][hb*16 + c], 16 contiguous half2 per w_k
    __half2* dst = &g_tmp_h[t][kd][0][hb * 16];
#pragma unroll 1
    for (int idx = threadIdx.x; idx < GS * 16; idx += 128){
        int w = idx >> 4, c = idx & 15;
        dst[w * GS + c] = sm1[w * 17 + c];
    }
}

// Pass 2: IDFT along h. grid=(40,16,3), block=256 (8 warps = 8 kd, 4 wk rows each).
__global__ void __launch_bounds__(256)
pass2_kernel()
{
    int t    = blockIdx.z;
    int kb   = blockIdx.y;            // kd group of 8
    int wb   = blockIdx.x;            // wk group of 4
    int wid  = threadIdx.x >> 5;      // 0..7 -> kd offset
    int lane = threadIdx.x & 31;
    int kd   = kb * 8 + wid;

    Tw tw; make_tw(tw, lane);

    __shared__ __half2 sm2[GS * 33];  // [h_k]*33 + ww*8 + wid  (k1*33%32 = k1)

#pragma unroll 1
    for (int ww = 0; ww < 4; ww++){
        int wk = wb * 4 + ww;
        const __half2* src = &g_tmp_h[t][kd][wk][0];
        float2 v[5], o[5];
#pragma unroll
        for (int j = 0; j < 5; j++)
            v[j] = __half22float2(src[5 * lane + j]);
        fft160(v, o, tw, lane);
#pragma unroll
        for (int k2 = 0; k2 < 5; k2++)
            sm2[(tw.k1 + 32 * k2) * 33 + ww * 8 + wid] =
                __floats2half2_rn(o[k2].x, o[k2].y);
    }
    __syncthreads();

    // write out: per h, 4 wk x 8 kd half2 -> 8 x uint4 (full 32B sectors)
#pragma unroll 1
    for (int idx = threadIdx.x; idx < GS * 8; idx += 256){
        int h = idx >> 3, rem = idx & 7, ww = rem >> 1, q = rem & 1;
        const __half2* p = &sm2[h * 33 + ww * 8 + q * 4];
        uint4 val;
        val.x = *(const unsigned*)&p[0];
        val.y = *(const unsigned*)&p[1];
        val.z = *(const unsigned*)&p[2];
        val.w = *(const unsigned*)&p[3];
        *(uint4*)&g_field_h[t][h][wb * 4 + ww][kb * 8 + q * 4] = val;
    }
}

// One warp per point. Lane L owns kd = 4L..4L+3.
__global__ void sample_kernel(const float* __restrict__ xyz,
                              const float* __restrict__ boundp,
                              float* __restrict__ out, int npts)
{
    int gw   = (int)((blockIdx.x * (unsigned)blockDim.x + threadIdx.x) >> 5);
    int lane = threadIdx.x & 31;
    if (gw >= npts) return;

    float invb = 1.0f / boundp[0];
    float px = xyz[3*gw + 0] * invb;
    float py = xyz[3*gw + 1] * invb;
    float pz = xyz[3*gw + 2] * invb;

    bool hi = (lane & 1) != 0;
    float gacc = 0.0f;

    const __half2* fld = &g_field_h[0][0][0][0];

#pragma unroll
    for (int t = 0; t < 3; t++){
        float gx = (t == 2) ? px : pz;
        float gy = (t == 1) ? px : py;
        float mc = (t == 0) ? px : ((t == 1) ? py : pz);

        float ix = (gx + 1.0f) * 0.5f * 159.0f;
        float iy = (gy + 1.0f) * 0.5f * 159.0f;
        float fx = floorf(ix), fy = floorf(iy);
        float wx = ix - fx,    wy = iy - fy;
        int i0 = (int)fx, j0 = (int)fy;
        int i1 = i0 + 1,  j1 = j0 + 1;

        float vx0 = (i0 >= 0 && i0 <= 159) ? 1.0f : 0.0f;
        float vx1 = (i1 >= 0 && i1 <= 159) ? 1.0f : 0.0f;
        float vy0 = (j0 >= 0 && j0 <= 159) ? 1.0f : 0.0f;
        float vy1 = (j1 >= 0 && j1 <= 159) ? 1.0f : 0.0f;
        int i0c = max(0, min(159, i0)), i1c = max(0, min(159, i1));
        int j0c = max(0, min(159, j0)), j1c = max(0, min(159, j1));

        __half2 w00h = __float2half2_rn((1.0f - wx) * (1.0f - wy) * vx0 * vy0);
        __half2 w01h = __float2half2_rn(wx          * (1.0f - wy) * vx1 * vy0);
        __half2 w10h = __float2half2_rn((1.0f - wx) * wy          * vx0 * vy1);
        __half2 w11h = __float2half2_rn(wx          * wy          * vx1 * vy1);

        int base = t * GS * GS * KD + lane * 4;
        uint4 u00 = *(const uint4*)(fld + base + (j0c * GS + i0c) * KD);
        uint4 u01 = *(const uint4*)(fld + base + (j0c * GS + i1c) * KD);
        uint4 u10 = *(const uint4*)(fld + base + (j1c * GS + i0c) * KD);
        uint4 u11 = *(const uint4*)(fld + base + (j1c * GS + i1c) * KD);

        float2 R[4];
#pragma unroll
        for (int c = 0; c < 4; c++){
            __half2 ha = *(__half2*)&((&u00.x)[c]);
            __half2 hb = *(__half2*)&((&u01.x)[c]);
            __half2 he = *(__half2*)&((&u10.x)[c]);
            __half2 hf = *(__half2*)&((&u11.x)[c]);
            __half2 acc = __hmul2(ha, w00h);
            acc = __hfma2(hb, w01h, acc);
            acc = __hfma2(he, w10h, acc);
            acc = __hfma2(hf, w11h, acc);
            R[c] = __half22float2(acc);
        }

        // modulation: FREQ = 0,1,2,4,8,16,32,64 via angle doubling
        float xt = (mc + 1.0f) * 0.5f;
        float s1, c1;
        sincospif(2.0f * xt, &s1, &c1);
        float cd[8], sd[8];
        cd[0] = 1.0f; sd[0] = 0.0f;
        float cc = c1, ss = s1;
        cd[1] = 2.0f * cc; sd[1] = 2.0f * ss;
#pragma unroll
        for (int j = 2; j < 8; j++){
            float nc = cc * cc - ss * ss;
            float ns = 2.0f * cc * ss;
            cc = nc; ss = ns;
            cd[j] = 2.0f * cc; sd[j] = 2.0f * ss;
        }
        float c0s = hi ? cd[4] : cd[0], s0s = hi ? sd[4] : sd[0];
        float c1s = hi ? cd[5] : cd[1], s1s = hi ? sd[5] : sd[1];
        float c2s = hi ? cd[6] : cd[2], s2s = hi ? sd[6] : sd[2];
        float c3s = hi ? cd[7] : cd[3], s3s = hi ? sd[7] : sd[3];

        gacc += R[0].x * c0s - R[0].y * s0s
              + R[1].x * c1s - R[1].y * s1s
              + R[2].x * c2s - R[2].y * s2s
              + R[3].x * c3s - R[3].y * s3s;
    }

    gacc *= INV_FSCALE;
    gacc += __shfl_xor_sync(0xffffffffu, gacc, 1);
    // compact: lane m picks partial of k=m from lane 2m -> coalesced 64B write
    float vv = __shfl_sync(0xffffffffu, gacc, (lane * 2) & 31);
    if (lane < NKS)
        out[gw * NKS + lane] = vv;
}

extern "C" void kernel_launch(void* const* d_in, const int* in_sizes, int n_in,
                              void* d_out, int out_size)
{
    const float* xyz   = (const float*)d_in[0];
    const float* bound = (const float*)d_in[1];
    const float* alpha = (const float*)d_in[2];
    const float* pur   = (const float*)d_in[3];
    const float* pui   = (const float*)d_in[4];
    const float* pvr   = (const float*)d_in[5];
    const float* pvi   = (const float*)d_in[6];
    const float* pwr   = (const float*)d_in[7];
    const float* pwi   = (const float*)d_in[8];

    dim3 g1(10, 128, 3);
    pass1_kernel<<<g1, 128>>>(pur, pui, pvr, pvi, pwr, pwi, alpha);

    dim3 g2(40, 16, 3);
    pass2_kernel<<<g2, 256>>>();

    int npts = in_sizes[0] / 3;
    int nblocks = (npts * 32 + 255) / 256;
    sample_kernel<<<nblocks, 256>>>(xyz, bound, (float*)d_out, npts);
}

// round 5
// speedup vs baseline: 1.6834x; 1.0082x over previous
#include <cuda_runtime.h>
#include <cuda_fp16.h>
#include <math.h>

#define GS   160
#define KD   128
#define NKS  16
#define FSCALE      262144.0f            // 2^18
#define INV_FSCALE  3.814697265625e-06f  // 2^-18

// Intermediates / field in fp16 (values pre-scaled by FSCALE).
__device__ __half2 g_tmp_h[3][KD][GS][GS];     // [t][kd][a_k][b]
__device__ __half2 g_field_h[3][GS][GS][KD];   // [t][h][w][kd]

struct Tw {
    float2 stw[5];
    float2 ta[5];
    float2 t5[5];
    int    k1;
};

__device__ __forceinline__ float2 cmulf(float2 a, float2 b){
    return make_float2(a.x*b.x - a.y*b.y, a.x*b.y + a.y*b.x);
}

__device__ __forceinline__ float softplus_scale(const float* __restrict__ alpha_params){
    float a0 = alpha_params[0];
    float bx = 10.0f * a0;
    float alpha = (bx > 1.0f) ? a0 : (log1pf(expf(fminf(bx, 1.0f))) * 0.1f);
    return alpha * (1.0f / 25600.0f) * FSCALE;
}

__device__ __forceinline__ void make_tw(Tw &tw, int lane){
#pragma unroll
    for (int s = 0; s < 5; s++){
        int H = 16 >> s;
        int j = lane & (H - 1);
        float sv, cv;
        sincospif((float)j / (float)H, &sv, &cv);
        tw.stw[s] = make_float2(cv, sv);
    }
    int k1 = (int)(__brev((unsigned)lane) >> 27);
    tw.k1 = k1;
#pragma unroll
    for (int n2 = 0; n2 < 5; n2++){
        float sv, cv;
        sincospif((float)(n2 * k1) / 80.0f, &sv, &cv);
        tw.ta[n2] = make_float2(cv, sv);
    }
#pragma unroll
    for (int m = 0; m < 5; m++){
        float sv, cv;
        sincospif(0.4f * (float)m, &sv, &cv);
        tw.t5[m] = make_float2(cv, sv);
    }
}

// Inverse-sign DFT-160 across a warp: in v[j]=x[5L+j], out o[k2]=X[k1+32k2].
__device__ __forceinline__ void fft160(float2 v[5], float2 o[5], const Tw &tw, int lane){
#pragma unroll
    for (int s = 0; s < 5; s++){
        int H = 16 >> s;
        float2 t = tw.stw[s];
        bool up = (lane & H) != 0;
#pragma unroll
        for (int j = 0; j < 5; j++){
            float pr = __shfl_xor_sync(0xffffffffu, v[j].x, H);
            float pi = __shfl_xor_sync(0xffffffffu, v[j].y, H);
            float lr = v[j].x + pr;
            float li = v[j].y + pi;
            float dr = pr - v[j].x;
            float di = pi - v[j].y;
            float ur = dr * t.x - di * t.y;
            float ui = dr * t.y + di * t.x;
            v[j].x = up ? ur : lr;
            v[j].y = up ? ui : li;
        }
    }
    float2 B[5];
#pragma unroll
    for (int n2 = 0; n2 < 5; n2++) B[n2] = cmulf(v[n2], tw.ta[n2]);
#pragma unroll
    for (int k2 = 0; k2 < 5; k2++){
        float2 acc = B[0];
#pragma unroll
        for (int n2 = 1; n2 < 5; n2++){
            float2 w = tw.t5[(n2 * k2) % 5];
            acc.x += B[n2].x * w.x - B[n2].y * w.y;
            acc.y += B[n2].x * w.y + B[n2].y * w.x;
        }
        o[k2] = acc;
    }
}

// Pass 1 for Pu (t=0) and Pv (t=1): contiguous-axis loads.
// grid=(5, 128, 2), block=128 (4 warps x 8 rows = 32 rows/block).
__global__ void __launch_bounds__(128)
pass1_t01_kernel(const float* __restrict__ pur, const float* __restrict__ pui,
                 const float* __restrict__ pvr, const float* __restrict__ pvi,
                 const float* __restrict__ alpha_params)
{
    int t    = blockIdx.z;            // 0 or 1
    int kd   = blockIdx.y;
    int bx   = blockIdx.x;            // 32 rows per block
    int wid  = threadIdx.x >> 5;
    int lane = threadIdx.x & 31;

    float scale = softplus_scale(alpha_params);
    const float* re = (t == 0) ? pur : pvr;
    const float* im = (t == 0) ? pui : pvi;
    int k = kd >> 3, d = kd & 7;

    Tw tw; make_tw(tw, lane);

    __shared__ __half2 sm1[GS * 33];   // [a_k]*33 + rowlocal(0..31)

#pragma unroll 1
    for (int r = 0; r < 8; r++){
        int rl = wid * 8 + r;
        int b  = bx * 32 + rl;
        float2 v[5], o[5];
#pragma unroll
        for (int j = 0; j < 5; j++){
            int a = 5 * lane + j;
            int idx = (t == 0) ? ((kd * GS + b) * GS + a)
                               : (((k * GS + b) * 8 + d) * GS + a);
            v[j] = make_float2(re[idx] * scale, im[idx] * scale);
        }
        fft160(v, o, tw, lane);
#pragma unroll
        for (int k2 = 0; k2 < 5; k2++)
            sm1[(tw.k1 + 32 * k2) * 33 + rl] = __floats2half2_rn(o[k2].x, o[k2].y);
    }
    __syncthreads();

    // writeout: per (a_k): 32 contiguous half2 = 128B. Build uint4 from 4 LDS.32.
#pragma unroll 1
    for (int idx = threadIdx.x; idx < GS * 8; idx += 128){
        int w = idx >> 3, g = idx & 7;
        const __half2* p = &sm1[w * 33 + g * 4];
        uint4 val;
        val.x = *(const unsigned*)&p[0];
        val.y = *(const unsigned*)&p[1];
        val.z = *(const unsigned*)&p[2];
        val.w = *(const unsigned*)&p[3];
        *(uint4*)&g_tmp_h[t][kd][w][bx * 32 + g * 4] = val;
    }
}

// Pass 1 for Pw (t=2): FFT along X with Y fixed; layout (k, X, Y, d).
// Block handles (k, 4 Y-rows, all 8 d). grid=(40, 16), block=256 (8 warps = 8 d).
// Coalesced staging: per X, the 4y x 8d floats are one 128B chunk.
__global__ void __launch_bounds__(256)
pass1_w_kernel(const float* __restrict__ pwr, const float* __restrict__ pwi,
               const float* __restrict__ alpha_params)
{
    int yb   = blockIdx.x;            // 4 Y rows
    int k    = blockIdx.y;
    int wid  = threadIdx.x >> 5;      // d
    int lane = threadIdx.x & 31;

    float scale = softplus_scale(alpha_params);

    __shared__ unsigned smw[4 * 1440];     // half2(re,im): [y][X*9 + d] (pad 9)
    __shared__ __half2  sm1w[8 * 800];     // [d][x_k*5 + y]

    // ---- stage: load 160 X-chunks of (4y x 8d) floats, pack to half2 ----
    {
        const float4* re4 = (const float4*)pwr;
        const float4* im4 = (const float4*)pwi;
        int y0 = yb * 4;
#pragma unroll 1
        for (int i = threadIdx.x; i < 1280; i += 256){
            int X   = i >> 3;
            int rem = i & 7;
            int y   = rem >> 1;
            int dg  = (rem & 1) * 4;
            int gidx = ((k * GS + X) * GS + y0 + y) * 2 + (rem & 1);
            float4 fr = re4[gidx];
            float4 fi = im4[gidx];
            unsigned* dst = &smw[y * 1440 + X * 9 + dg];
            __half2 h0 = __floats2half2_rn(fr.x * scale, fi.x * scale);
            __half2 h1 = __floats2half2_rn(fr.y * scale, fi.y * scale);
            __half2 h2 = __floats2half2_rn(fr.z * scale, fi.z * scale);
            __half2 h3 = __floats2half2_rn(fr.w * scale, fi.w * scale);
            dst[0] = *(unsigned*)&h0;
            dst[1] = *(unsigned*)&h1;
            dst[2] = *(unsigned*)&h2;
            dst[3] = *(unsigned*)&h3;
        }
    }
    __syncthreads();

    // ---- FFT along X: warp wid handles d=wid, 4 Y rows ----
    Tw tw; make_tw(tw, lane);
#pragma unroll 1
    for (int r = 0; r < 4; r++){
        float2 v[5], o[5];
#pragma unroll
        for (int j = 0; j < 5; j++){
            unsigned u = smw[r * 1440 + (5 * lane + j) * 9 + wid];
            v[j] = __half22float2(*(__half2*)&u);
        }
        fft160(v, o, tw, lane);
#pragma unroll
        for (int k2 = 0; k2 < 5; k2++)
            sm1w[wid * 800 + (tw.k1 + 32 * k2) * 5 + r] =
                __floats2half2_rn(o[k2].x, o[k2].y);
    }
    __syncthreads();

    // ---- writeout: g_tmp[2][k*8+d][x_k][yb*4 + 0..3] as uint4 ----
#pragma unroll 1
    for (int i = threadIdx.x; i < 1280; i += 256){
        int d = i / 160;
        int x = i - d * 160;
        const __half2* p = &sm1w[d * 800 + x * 5];
        uint4 val;
        val.x = *(const unsigned*)&p[0];
        val.y = *(const unsigned*)&p[1];
        val.z = *(const unsigned*)&p[2];
        val.w = *(const unsigned*)&p[3];
        *(uint4*)&g_tmp_h[2][k * 8 + d][x][yb * 4] = val;
    }
}

// Pass 2: IDFT along b-axis. grid=(20,16,3), block=256 (8 warps = 8 kd, 8 wk each).
__global__ void __launch_bounds__(256)
pass2_kernel()
{
    int t    = blockIdx.z;
    int kb   = blockIdx.y;            // kd group of 8
    int wb   = blockIdx.x;            // wk group of 8
    int wid  = threadIdx.x >> 5;
    int lane = threadIdx.x & 31;
    int kd   = kb * 8 + wid;

    Tw tw; make_tw(tw, lane);

    __shared__ __half2 sm2[GS * 65];  // [h_k]*65 + ww*8 + wid

#pragma unroll 1
    for (int ww = 0; ww < 8; ww++){
        int wk = wb * 8 + ww;
        const __half2* src = &g_tmp_h[t][kd][wk][0];
        float2 v[5], o[5];
#pragma unroll
        for (int j = 0; j < 5; j++)
            v[j] = __half22float2(src[5 * lane + j]);
        fft160(v, o, tw, lane);
#pragma unroll
        for (int k2 = 0; k2 < 5; k2++)
            sm2[(tw.k1 + 32 * k2) * 65 + ww * 8 + wid] =
                __floats2half2_rn(o[k2].x, o[k2].y);
    }
    __syncthreads();

    // writeout: per (h, wk): 8 kd half2 = 32B = 2 x uint4
#pragma unroll 1
    for (int idx = threadIdx.x; idx < GS * 16; idx += 256){
        int h = idx >> 4, rem = idx & 15, ww = rem >> 1, q = rem & 1;
        const __half2* p = &sm2[h * 65 + ww * 8 + q * 4];
        uint4 val;
        val.x = *(const unsigned*)&p[0];
        val.y = *(const unsigned*)&p[1];
        val.z = *(const unsigned*)&p[2];
        val.w = *(const unsigned*)&p[3];
        *(uint4*)&g_field_h[t][h][wb * 8 + ww][kb * 8 + q * 4] = val;
    }
}

// One warp per point. Lane L owns kd = 4L..4L+3.
__global__ void sample_kernel(const float* __restrict__ xyz,
                              const float* __restrict__ boundp,
                              float* __restrict__ out, int npts)
{
    int gw   = (int)((blockIdx.x * (unsigned)blockDim.x + threadIdx.x) >> 5);
    int lane = threadIdx.x & 31;
    if (gw >= npts) return;

    float invb = 1.0f / boundp[0];
    float px = xyz[3*gw + 0] * invb;
    float py = xyz[3*gw + 1] * invb;
    float pz = xyz[3*gw + 2] * invb;

    bool hi = (lane & 1) != 0;
    float gacc = 0.0f;

    const __half2* fld = &g_field_h[0][0][0][0];

#pragma unroll
    for (int t = 0; t < 3; t++){
        float gx = (t == 2) ? px : pz;
        float gy = (t == 1) ? px : py;
        float mc = (t == 0) ? px : ((t == 1) ? py : pz);

        float ix = (gx + 1.0f) * 0.5f * 159.0f;
        float iy = (gy + 1.0f) * 0.5f * 159.0f;
        float fx = floorf(ix), fy = floorf(iy);
        float wx = ix - fx,    wy = iy - fy;
        int i0 = (int)fx, j0 = (int)fy;
        int i1 = i0 + 1,  j1 = j0 + 1;

        float vx0 = (i0 >= 0 && i0 <= 159) ? 1.0f : 0.0f;
        float vx1 = (i1 >= 0 && i1 <= 159) ? 1.0f : 0.0f;
        float vy0 = (j0 >= 0 && j0 <= 159) ? 1.0f : 0.0f;
        float vy1 = (j1 >= 0 && j1 <= 159) ? 1.0f : 0.0f;
        int i0c = max(0, min(159, i0)), i1c = max(0, min(159, i1));
        int j0c = max(0, min(159, j0)), j1c = max(0, min(159, j1));

        __half2 w00h = __float2half2_rn((1.0f - wx) * (1.0f - wy) * vx0 * vy0);
        __half2 w01h = __float2half2_rn(wx          * (1.0f - wy) * vx1 * vy0);
        __half2 w10h = __float2half2_rn((1.0f - wx) * wy          * vx0 * vy1);
        __half2 w11h = __float2half2_rn(wx          * wy          * vx1 * vy1);

        int base = t * GS * GS * KD + lane * 4;
        uint4 u00 = *(const uint4*)(fld + base + (j0c * GS + i0c) * KD);
        uint4 u01 = *(const uint4*)(fld + base + (j0c * GS + i1c) * KD);
        uint4 u10 = *(const uint4*)(fld + base + (j1c * GS + i0c) * KD);
        uint4 u11 = *(const uint4*)(fld + base + (j1c * GS + i1c) * KD);

        float2 R[4];
#pragma unroll
        for (int c = 0; c < 4; c++){
            __half2 ha = *(__half2*)&((&u00.x)[c]);
            __half2 hb = *(__half2*)&((&u01.x)[c]);
            __half2 he = *(__half2*)&((&u10.x)[c]);
            __half2 hf = *(__half2*)&((&u11.x)[c]);
            __half2 acc = __hmul2(ha, w00h);
            acc = __hfma2(hb, w01h, acc);
            acc = __hfma2(he, w10h, acc);
            acc = __hfma2(hf, w11h, acc);
            R[c] = __half22float2(acc);
        }

        float xt = (mc + 1.0f) * 0.5f;
        float s1, c1;
        sincospif(2.0f * xt, &s1, &c1);
        float cd[8], sd[8];
        cd[0] = 1.0f; sd[0] = 0.0f;
        float cc = c1, ss = s1;
        cd[1] = 2.0f * cc; sd[1] = 2.0f * ss;
#pragma unroll
        for (int j = 2; j < 8; j++){
            float nc = cc * cc - ss * ss;
            float ns = 2.0f * cc * ss;
            cc = nc; ss = ns;
            cd[j] = 2.0f * cc; sd[j] = 2.0f * ss;
        }
        float c0s = hi ? cd[4] : cd[0], s0s = hi ? sd[4] : sd[0];
        float c1s = hi ? cd[5] : cd[1], s1s = hi ? sd[5] : sd[1];
        float c2s = hi ? cd[6] : cd[2], s2s = hi ? sd[6] : sd[2];
        float c3s = hi ? cd[7] : cd[3], s3s = hi ? sd[7] : sd[3];

        gacc += R[0].x * c0s - R[0].y * s0s
              + R[1].x * c1s - R[1].y * s1s
              + R[2].x * c2s - R[2].y * s2s
              + R[3].x * c3s - R[3].y * s3s;
    }

    gacc *= INV_FSCALE;
    gacc += __shfl_xor_sync(0xffffffffu, gacc, 1);
    float vv = __shfl_sync(0xffffffffu, gacc, (lane * 2) & 31);
    if (lane < NKS)
        out[gw * NKS + lane] = vv;
}

extern "C" void kernel_launch(void* const* d_in, const int* in_sizes, int n_in,
                              void* d_out, int out_size)
{
    const float* xyz   = (const float*)d_in[0];
    const float* bound = (const float*)d_in[1];
    const float* alpha = (const float*)d_in[2];
    const float* pur   = (const float*)d_in[3];
    const float* pui   = (const float*)d_in[4];
    const float* pvr   = (const float*)d_in[5];
    const float* pvi   = (const float*)d_in[6];
    const float* pwr   = (const float*)d_in[7];
    const float* pwi   = (const float*)d_in[8];

    dim3 g1(5, 128, 2);
    pass1_t01_kernel<<<g1, 128>>>(pur, pui, pvr, pvi, alpha);

    dim3 gw(40, 16);
    pass1_w_kernel<<<gw, 256>>>(pwr, pwi, alpha);

    dim3 g2(20, 16, 3);
    pass2_kernel<<<g2, 256>>>();

    int npts = in_sizes[0] / 3;
    int nblocks = (npts * 32 + 255) / 256;
    sample_kernel<<<nblocks, 256>>>(xyz, bound, (float*)d_out, npts);
}

// round 6
// speedup vs baseline: 1.8816x; 1.1178x over previous
#include <cuda_runtime.h>
#include <cuda_fp16.h>
#include <math.h>

#define GS   160
#define KD   128
#define NKS  16
#define FSCALE      262144.0f            // 2^18
#define INV_FSCALE  3.814697265625e-06f  // 2^-18

// Intermediates / field in fp16 (values pre-scaled by FSCALE).
__device__ __half2 g_tmp_h[3][KD][GS][GS];     // [t][kd][a_k][b]
__device__ __half2 g_field_h[3][GS][GS][KD];   // [t][h][w][kd]

struct Tw {
    float2 stw[5];   // butterfly stage twiddles e^{+2pi i (lane&(H-1))/(2H)}
    float2 ta[5];    // e^{+2pi i lane*r/160}
    float2 t5[5];    // e^{+2pi i m/5}
    int    k1;       // brev5(lane)
};

__device__ __forceinline__ float2 cmulf(float2 a, float2 b){
    return make_float2(a.x*b.x - a.y*b.y, a.x*b.y + a.y*b.x);
}

__device__ __forceinline__ float softplus_scale(const float* __restrict__ alpha_params){
    float a0 = alpha_params[0];
    float bx = 10.0f * a0;
    float alpha = (bx > 1.0f) ? a0 : (log1pf(expf(fminf(bx, 1.0f))) * 0.1f);
    return alpha * (1.0f / 25600.0f) * FSCALE;
}

__device__ __forceinline__ void make_tw(Tw &tw, int lane){
#pragma unroll
    for (int s = 0; s < 5; s++){
        int H = 16 >> s;
        int j = lane & (H - 1);
        float sv, cv;
        sincospif((float)j / (float)H, &sv, &cv);
        tw.stw[s] = make_float2(cv, sv);
    }
    tw.k1 = (int)(__brev((unsigned)lane) >> 27);
#pragma unroll
    for (int r = 0; r < 5; r++){
        float sv, cv;
        sincospif((float)(lane * r) / 80.0f, &sv, &cv);   // 2pi*lane*r/160
        tw.ta[r] = make_float2(cv, sv);
    }
#pragma unroll
    for (int m = 0; m < 5; m++){
        float sv, cv;
        sincospif(0.4f * (float)m, &sv, &cv);             // 2pi*m/5
        tw.t5[m] = make_float2(cv, sv);
    }
}

// Inverse-sign DFT-160 across a warp, stride-1 input mapping.
// Input : lane L, v[j] = x[L + 32*j], j=0..4
// Output: o[r]   = X[r + 5*brev5(L)],  X[k] = sum_n x[n] e^{+2pi i nk/160}
// Derivation: X[r+5q] = DFT32_q( e^{2pi i n1 r/160} * DFT5_r(x[n1+32*n2]) )
__device__ __forceinline__ void fft160(float2 v[5], float2 o[5], const Tw &tw, int lane){
    // lane-local DFT-5 over j, then twiddle ta[r]
#pragma unroll
    for (int r = 0; r < 5; r++){
        float2 acc = v[0];
#pragma unroll
        for (int j = 1; j < 5; j++){
            float2 w = tw.t5[(j * r) % 5];
            acc.x += v[j].x * w.x - v[j].y * w.y;
            acc.y += v[j].x * w.y + v[j].y * w.x;
        }
        o[r] = cmulf(acc, tw.ta[r]);
    }
    // DFT-32 across lanes (DIF radix-2, output bit-reversed in lane)
#pragma unroll
    for (int s = 0; s < 5; s++){
        int H = 16 >> s;
        float2 t = tw.stw[s];
        bool up = (lane & H) != 0;
#pragma unroll
        for (int r = 0; r < 5; r++){
            float pr = __shfl_xor_sync(0xffffffffu, o[r].x, H);
            float pi = __shfl_xor_sync(0xffffffffu, o[r].y, H);
            float lr = o[r].x + pr;
            float li = o[r].y + pi;
            float dr = pr - o[r].x;
            float di = pi - o[r].y;
            float ur = dr * t.x - di * t.y;
            float ui = dr * t.y + di * t.x;
            o[r].x = up ? ur : lr;
            o[r].y = up ? ui : li;
        }
    }
}

// Pass 1 for Pu (t=0) and Pv (t=1): stride-1 coalesced loads.
// grid=(5, 128, 2), block=128 (4 warps x 8 rows = 32 rows/block).
__global__ void __launch_bounds__(128)
pass1_t01_kernel(const float* __restrict__ pur, const float* __restrict__ pui,
                 const float* __restrict__ pvr, const float* __restrict__ pvi,
                 const float* __restrict__ alpha_params)
{
    int t    = blockIdx.z;
    int kd   = blockIdx.y;
    int bx   = blockIdx.x;
    int wid  = threadIdx.x >> 5;
    int lane = threadIdx.x & 31;

    float scale = softplus_scale(alpha_params);
    const float* re = (t == 0) ? pur : pvr;
    const float* im = (t == 0) ? pui : pvi;
    int k = kd >> 3, d = kd & 7;

    Tw tw; make_tw(tw, lane);

    __shared__ __half2 sm1[GS * 33];   // [a_k]*33 + rowlocal(0..31)

#pragma unroll 1
    for (int r = 0; r < 8; r++){
        int rl = wid * 8 + r;
        int b  = bx * 32 + rl;
        int base = (t == 0) ? ((kd * GS + b) * GS)
                            : (((k * GS + b) * 8 + d) * GS);
        float2 v[5], o[5];
#pragma unroll
        for (int j = 0; j < 5; j++){
            int idx = base + lane + 32 * j;        // stride-1 across lanes
            v[j] = make_float2(re[idx] * scale, im[idx] * scale);
        }
        fft160(v, o, tw, lane);
#pragma unroll
        for (int r2 = 0; r2 < 5; r2++)
            sm1[(r2 + 5 * tw.k1) * 33 + rl] = __floats2half2_rn(o[r2].x, o[r2].y);
    }
    __syncthreads();

    // writeout: per (a_k): 32 contiguous half2 = 128B
#pragma unroll 1
    for (int idx = threadIdx.x; idx < GS * 8; idx += 128){
        int w = idx >> 3, g = idx & 7;
        const __half2* p = &sm1[w * 33 + g * 4];
        uint4 val;
        val.x = *(const unsigned*)&p[0];
        val.y = *(const unsigned*)&p[1];
        val.z = *(const unsigned*)&p[2];
        val.w = *(const unsigned*)&p[3];
        *(uint4*)&g_tmp_h[t][kd][w][bx * 32 + g * 4] = val;
    }
}

// Pass 1 for Pw (t=2): smem-staged, coalesced float4 loads.
// grid=(40, 16), block=256 (8 warps = 8 d).
__global__ void __launch_bounds__(256)
pass1_w_kernel(const float* __restrict__ pwr, const float* __restrict__ pwi,
               const float* __restrict__ alpha_params)
{
    int yb   = blockIdx.x;            // 4 Y rows
    int k    = blockIdx.y;
    int wid  = threadIdx.x >> 5;      // d
    int lane = threadIdx.x & 31;

    float scale = softplus_scale(alpha_params);

    __shared__ unsigned smw[4 * 1440];     // [y][X*9 + d] (pad 9)
    __shared__ __half2  sm1w[8 * 800];     // [d][x_k*5 + y]

    {
        const float4* re4 = (const float4*)pwr;
        const float4* im4 = (const float4*)pwi;
        int y0 = yb * 4;
#pragma unroll 1
        for (int i = threadIdx.x; i < 1280; i += 256){
            int X   = i >> 3;
            int rem = i & 7;
            int y   = rem >> 1;
            int dg  = (rem & 1) * 4;
            int gidx = ((k * GS + X) * GS + y0 + y) * 2 + (rem & 1);
            float4 fr = re4[gidx];
            float4 fi = im4[gidx];
            unsigned* dst = &smw[y * 1440 + X * 9 + dg];
            __half2 h0 = __floats2half2_rn(fr.x * scale, fi.x * scale);
            __half2 h1 = __floats2half2_rn(fr.y * scale, fi.y * scale);
            __half2 h2 = __floats2half2_rn(fr.z * scale, fi.z * scale);
            __half2 h3 = __floats2half2_rn(fr.w * scale, fi.w * scale);
            dst[0] = *(unsigned*)&h0;
            dst[1] = *(unsigned*)&h1;
            dst[2] = *(unsigned*)&h2;
            dst[3] = *(unsigned*)&h3;
        }
    }
    __syncthreads();

    Tw tw; make_tw(tw, lane);
#pragma unroll 1
    for (int yr = 0; yr < 4; yr++){
        float2 v[5], o[5];
#pragma unroll
        for (int j = 0; j < 5; j++){
            unsigned u = smw[yr * 1440 + (lane + 32 * j) * 9 + wid];
            v[j] = __half22float2(*(__half2*)&u);
        }
        fft160(v, o, tw, lane);
#pragma unroll
        for (int r2 = 0; r2 < 5; r2++)
            sm1w[wid * 800 + (r2 + 5 * tw.k1) * 5 + yr] =
                __floats2half2_rn(o[r2].x, o[r2].y);
    }
    __syncthreads();

#pragma unroll 1
    for (int i = threadIdx.x; i < 1280; i += 256){
        int d = i / 160;
        int x = i - d * 160;
        const __half2* p = &sm1w[d * 800 + x * 5];
        uint4 val;
        val.x = *(const unsigned*)&p[0];
        val.y = *(const unsigned*)&p[1];
        val.z = *(const unsigned*)&p[2];
        val.w = *(const unsigned*)&p[3];
        *(uint4*)&g_tmp_h[2][k * 8 + d][x][yb * 4] = val;
    }
}

// Pass 2: IDFT along b-axis. grid=(20,16,3), block=256 (8 warps = 8 kd, 8 wk each).
__global__ void __launch_bounds__(256)
pass2_kernel()
{
    int t    = blockIdx.z;
    int kb   = blockIdx.y;
    int wb   = blockIdx.x;
    int wid  = threadIdx.x >> 5;
    int lane = threadIdx.x & 31;
    int kd   = kb * 8 + wid;

    Tw tw; make_tw(tw, lane);

    __shared__ __half2 sm2[GS * 65];  // [h_k]*65 + ww*8 + wid

#pragma unroll 1
    for (int ww = 0; ww < 8; ww++){
        int wk = wb * 8 + ww;
        const __half2* src = &g_tmp_h[t][kd][wk][0];
        float2 v[5], o[5];
#pragma unroll
        for (int j = 0; j < 5; j++)
            v[j] = __half22float2(src[lane + 32 * j]);    // stride-1 coalesced
        fft160(v, o, tw, lane);
#pragma unroll
        for (int r2 = 0; r2 < 5; r2++)
            sm2[(r2 + 5 * tw.k1) * 65 + ww * 8 + wid] =
                __floats2half2_rn(o[r2].x, o[r2].y);
    }
    __syncthreads();

#pragma unroll 1
    for (int idx = threadIdx.x; idx < GS * 16; idx += 256){
        int h = idx >> 4, rem = idx & 15, ww = rem >> 1, q = rem & 1;
        const __half2* p = &sm2[h * 65 + ww * 8 + q * 4];
        uint4 val;
        val.x = *(const unsigned*)&p[0];
        val.y = *(const unsigned*)&p[1];
        val.z = *(const unsigned*)&p[2];
        val.w = *(const unsigned*)&p[3];
        *(uint4*)&g_field_h[t][h][wb * 8 + ww][kb * 8 + q * 4] = val;
    }
}

// Sample: 16 lanes per point (2 points/warp). Lane sl owns k = sl, all 8 d.
__global__ void __launch_bounds__(256)
sample_kernel(const float* __restrict__ xyz,
              const float* __restrict__ boundp,
              float* __restrict__ out, int npts)
{
    int warp_g = (int)((blockIdx.x * (unsigned)blockDim.x + threadIdx.x) >> 5);
    int lane = threadIdx.x & 31;
    int sub  = lane >> 4;          // which point in the warp
    int sl   = lane & 15;          // k index
    int gw   = warp_g * 2 + sub;
    if (gw >= npts) return;

    float invb = 1.0f / boundp[0];
    float p[3];
    p[0] = xyz[3*gw + 0] * invb;
    p[1] = xyz[3*gw + 1] * invb;
    p[2] = xyz[3*gw + 2] * invb;

    // per-axis sampling data (each axis reused by 2 tensors)
    float wa0[3], wa1[3];
    int   c0i[3], c1i[3];
#pragma unroll
    for (int a = 0; a < 3; a++){
        float ia = (p[a] + 1.0f) * 0.5f * 159.0f;
        float fl = floorf(ia);
        float w  = ia - fl;
        int i0 = (int)fl, i1 = i0 + 1;
        float v0 = (i0 >= 0 && i0 <= 159) ? 1.0f : 0.0f;
        float v1 = (i1 >= 0 && i1 <= 159) ? 1.0f : 0.0f;
        c0i[a] = max(0, min(159, i0));
        c1i[a] = max(0, min(159, i1));
        wa0[a] = (1.0f - w) * v0;
        wa1[a] = w * v1;
    }

    const __half2* fld = &g_field_h[0][0][0][0];
    float gacc = 0.0f;

#pragma unroll
    for (int t = 0; t < 3; t++){
        const int ax = (t == 2) ? 0 : 2;    // W axis
        const int ay = (t == 1) ? 0 : 1;    // H axis

        __half2 w00h = __float2half2_rn(wa0[ax] * wa0[ay]);
        __half2 w01h = __float2half2_rn(wa1[ax] * wa0[ay]);
        __half2 w10h = __float2half2_rn(wa0[ax] * wa1[ay]);
        __half2 w11h = __float2half2_rn(wa1[ax] * wa1[ay]);

        int i0 = c0i[ax], i1 = c1i[ax];
        int j0 = c0i[ay], j1 = c1i[ay];

        const __half2* bp = fld + t * GS * GS * KD + sl * 8;
        const uint4* p00 = (const uint4*)(bp + (j0 * GS + i0) * KD);
        const uint4* p01 = (const uint4*)(bp + (j0 * GS + i1) * KD);
        const uint4* p10 = (const uint4*)(bp + (j1 * GS + i0) * KD);
        const uint4* p11 = (const uint4*)(bp + (j1 * GS + i1) * KD);

        // modulation weights for all 8 freqs (0,1,2,4,8,16,32,64), scale 2 for f>0
        float xt = (p[t] + 1.0f) * 0.5f;
        float s1, c1;
        sincospif(2.0f * xt, &s1, &c1);
        float cd[8], sd[8];
        cd[0] = 1.0f; sd[0] = 0.0f;
        float cc = c1, ss = s1;
        cd[1] = 2.0f * cc; sd[1] = 2.0f * ss;
#pragma unroll
        for (int j = 2; j < 8; j++){
            float nc = cc * cc - ss * ss;
            float ns = 2.0f * cc * ss;
            cc = nc; ss = ns;
            cd[j] = 2.0f * cc; sd[j] = 2.0f * ss;
        }

#pragma unroll
        for (int hh = 0; hh < 2; hh++){
            uint4 u00 = p00[hh], u01 = p01[hh], u10 = p10[hh], u11 = p11[hh];
#pragma unroll
            for (int c = 0; c < 4; c++){
                __half2 acc = __hmul2(*(__half2*)&((&u00.x)[c]), w00h);
                acc = __hfma2(*(__half2*)&((&u01.x)[c]), w01h, acc);
                acc = __hfma2(*(__half2*)&((&u10.x)[c]), w10h, acc);
                acc = __hfma2(*(__half2*)&((&u11.x)[c]), w11h, acc);
                float2 f = __half22float2(acc);
                int d = hh * 4 + c;
                gacc += f.x * cd[d] - f.y * sd[d];
            }
        }
    }

    out[gw * NKS + sl] = gacc * INV_FSCALE;
}

extern "C" void kernel_launch(void* const* d_in, const int* in_sizes, int n_in,
                              void* d_out, int out_size)
{
    const float* xyz   = (const float*)d_in[0];
    const float* bound = (const float*)d_in[1];
    const float* alpha = (const float*)d_in[2];
    const float* pur   = (const float*)d_in[3];
    const float* pui   = (const float*)d_in[4];
    const float* pvr   = (const float*)d_in[5];
    const float* pvi   = (const float*)d_in[6];
    const float* pwr   = (const float*)d_in[7];
    const float* pwi   = (const float*)d_in[8];

    dim3 g1(5, 128, 2);
    pass1_t01_kernel<<<g1, 128>>>(pur, pui, pvr, pvi, alpha);

    dim3 gw(40, 16);
    pass1_w_kernel<<<gw, 256>>>(pwr, pwi, alpha);

    dim3 g2(20, 16, 3);
    pass2_kernel<<<g2, 256>>>();

    int npts = in_sizes[0] / 3;
    int nwarps = (npts + 1) / 2;
    int nblocks = (nwarps * 32 + 255) / 256;
    sample_kernel<<<nblocks, 256>>>(xyz, bound, (float*)d_out, npts);
}

// round 7
// speedup vs baseline: 2.1644x; 1.1503x over previous
#include <cuda_runtime.h>
#include <cuda_fp16.h>
#include <math.h>

#define GS   160
#define KD   128
#define NKS  16
#define FSCALE      262144.0f            // 2^18
#define INV_FSCALE  3.814697265625e-06f  // 2^-18

// Intermediates / field in fp16 (values pre-scaled by FSCALE).
__device__ __half2 g_tmp_h[3][KD][GS][GS];     // [t][kd][a_k][b]
__device__ __half2 g_field_h[3][GS][GS][KD];   // [t][h][w][kd]

struct Tw {
    float2 stw[5];   // per-lane stage twiddle: upper half e^{+i*pi*j/H}, lower half (1,0)
    float  sg[5];    // +1 lower half, -1 upper half
    float2 ta[4];    // e^{+2pi i lane*r/160}, r=1..4  (r=0 is unity)
    int    k1;       // brev5(lane)
};

__device__ __forceinline__ float2 cmulf(float2 a, float2 b){
    return make_float2(a.x*b.x - a.y*b.y, a.x*b.y + a.y*b.x);
}

__device__ __forceinline__ float softplus_scale(const float* __restrict__ alpha_params){
    float a0 = alpha_params[0];
    float bx = 10.0f * a0;
    float alpha = (bx > 1.0f) ? a0 : (log1pf(expf(fminf(bx, 1.0f))) * 0.1f);
    return alpha * (1.0f / 25600.0f) * FSCALE;
}

__device__ __forceinline__ void make_tw(Tw &tw, int lane){
#pragma unroll
    for (int s = 0; s < 5; s++){
        int H = 16 >> s;
        if (lane & H){
            int j = lane & (H - 1);
            float sv, cv;
            sincospif((float)j / (float)H, &sv, &cv);
            tw.stw[s] = make_float2(cv, sv);
            tw.sg[s]  = -1.0f;
        } else {
            tw.stw[s] = make_float2(1.0f, 0.0f);
            tw.sg[s]  = 1.0f;
        }
    }
    tw.k1 = (int)(__brev((unsigned)lane) >> 27);
#pragma unroll
    for (int r = 1; r < 5; r++){
        float sv, cv;
        sincospif((float)(lane * r) / 80.0f, &sv, &cv);   // 2pi*lane*r/160
        tw.ta[r - 1] = make_float2(cv, sv);
    }
}

// Inverse-sign DFT-160 across a warp, stride-1 input mapping.
// Input : lane L, v[j] = x[L + 32*j], j=0..4
// Output: o[r]   = X[r + 5*brev5(L)],  X[k] = sum_n x[n] e^{+2pi i nk/160}
__device__ __forceinline__ void fft160(float2 v[5], float2 o[5], const Tw &tw, int lane){
    // --- symmetric DFT-5 over j (w = e^{+2pi i/5}) ---
    const float C1 =  0.30901699437494745f;   // cos(2pi/5)
    const float C2 = -0.80901699437494734f;   // cos(4pi/5)
    const float S1 =  0.95105651629515353f;   // sin(2pi/5)
    const float S2 =  0.58778525229247314f;   // sin(4pi/5)
    float s1x = v[1].x + v[4].x, s1y = v[1].y + v[4].y;
    float d1x = v[1].x - v[4].x, d1y = v[1].y - v[4].y;
    float s2x = v[2].x + v[3].x, s2y = v[2].y + v[3].y;
    float d2x = v[2].x - v[3].x, d2y = v[2].y - v[3].y;

    o[0] = make_float2(v[0].x + s1x + s2x, v[0].y + s1y + s2y);

    float uax = v[0].x + C1 * s1x + C2 * s2x;
    float uay = v[0].y + C1 * s1y + C2 * s2y;
    float ubx = v[0].x + C2 * s1x + C1 * s2x;
    float uby = v[0].y + C2 * s1y + C1 * s2y;
    float wax = S1 * d1x + S2 * d2x;
    float way = S1 * d1y + S2 * d2y;
    float wbx = S2 * d1x - S1 * d2x;
    float wby = S2 * d1y - S1 * d2y;

    float2 X1 = make_float2(uax - way, uay + wax);
    float2 X4 = make_float2(uax + way, uay - wax);
    float2 X2 = make_float2(ubx - wby, uby + wbx);
    float2 X3 = make_float2(ubx + wby, uby - wbx);

    o[1] = cmulf(X1, tw.ta[0]);
    o[2] = cmulf(X2, tw.ta[1]);
    o[3] = cmulf(X3, tw.ta[2]);
    o[4] = cmulf(X4, tw.ta[3]);

    // --- DFT-32 across lanes (DIF radix-2, sign-folded, no selects) ---
#pragma unroll
    for (int s = 0; s < 5; s++){
        int H = 16 >> s;
        float2 t = tw.stw[s];
        float  g = tw.sg[s];
#pragma unroll
        for (int r = 0; r < 5; r++){
            float px = __shfl_xor_sync(0xffffffffu, o[r].x, H);
            float py = __shfl_xor_sync(0xffffffffu, o[r].y, H);
            float tx = fmaf(g, o[r].x, px);
            float ty = fmaf(g, o[r].y, py);
            o[r].x = tx * t.x - ty * t.y;
            o[r].y = tx * t.y + ty * t.x;
        }
    }
}

// Pass 1 for Pu (t=0) and Pv (t=1): stride-1 coalesced loads.
// grid=(5, 128, 2), block=128 (4 warps x 8 rows = 32 rows/block).
__global__ void __launch_bounds__(128)
pass1_t01_kernel(const float* __restrict__ pur, const float* __restrict__ pui,
                 const float* __restrict__ pvr, const float* __restrict__ pvi,
                 const float* __restrict__ alpha_params)
{
    int t    = blockIdx.z;
    int kd   = blockIdx.y;
    int bx   = blockIdx.x;
    int wid  = threadIdx.x >> 5;
    int lane = threadIdx.x & 31;

    float scale = softplus_scale(alpha_params);
    const float* re = (t == 0) ? pur : pvr;
    const float* im = (t == 0) ? pui : pvi;
    int k = kd >> 3, d = kd & 7;

    Tw tw; make_tw(tw, lane);

    __shared__ __half2 sm1[GS * 33];   // [a_k]*33 + rowlocal(0..31)

#pragma unroll 1
    for (int r = 0; r < 8; r++){
        int rl = wid * 8 + r;
        int b  = bx * 32 + rl;
        int base = (t == 0) ? ((kd * GS + b) * GS)
                            : (((k * GS + b) * 8 + d) * GS);
        float2 v[5], o[5];
#pragma unroll
        for (int j = 0; j < 5; j++){
            int idx = base + lane + 32 * j;
            v[j] = make_float2(re[idx] * scale, im[idx] * scale);
        }
        fft160(v, o, tw, lane);
#pragma unroll
        for (int r2 = 0; r2 < 5; r2++)
            sm1[(r2 + 5 * tw.k1) * 33 + rl] = __floats2half2_rn(o[r2].x, o[r2].y);
    }
    __syncthreads();

#pragma unroll 1
    for (int idx = threadIdx.x; idx < GS * 8; idx += 128){
        int w = idx >> 3, g = idx & 7;
        const __half2* p = &sm1[w * 33 + g * 4];
        uint4 val;
        val.x = *(const unsigned*)&p[0];
        val.y = *(const unsigned*)&p[1];
        val.z = *(const unsigned*)&p[2];
        val.w = *(const unsigned*)&p[3];
        *(uint4*)&g_tmp_h[t][kd][w][bx * 32 + g * 4] = val;
    }
}

// Pass 1 for Pw (t=2): smem-staged, coalesced float4 loads.
// grid=(40, 16), block=256 (8 warps = 8 d).
__global__ void __launch_bounds__(256)
pass1_w_kernel(const float* __restrict__ pwr, const float* __restrict__ pwi,
               const float* __restrict__ alpha_params)
{
    int yb   = blockIdx.x;            // 4 Y rows
    int k    = blockIdx.y;
    int wid  = threadIdx.x >> 5;      // d
    int lane = threadIdx.x & 31;

    float scale = softplus_scale(alpha_params);

    __shared__ unsigned smw[4 * 1440];     // [y][X*9 + d] (pad 9)
    __shared__ __half2  sm1w[8 * 800];     // [d][x_k*5 + y]

    {
        const float4* re4 = (const float4*)pwr;
        const float4* im4 = (const float4*)pwi;
        int y0 = yb * 4;
#pragma unroll 1
        for (int i = threadIdx.x; i < 1280; i += 256){
            int X   = i >> 3;
            int rem = i & 7;
            int y   = rem >> 1;
            int dg  = (rem & 1) * 4;
            int gidx = ((k * GS + X) * GS + y0 + y) * 2 + (rem & 1);
            float4 fr = re4[gidx];
            float4 fi = im4[gidx];
            unsigned* dst = &smw[y * 1440 + X * 9 + dg];
            __half2 h0 = __floats2half2_rn(fr.x * scale, fi.x * scale);
            __half2 h1 = __floats2half2_rn(fr.y * scale, fi.y * scale);
            __half2 h2 = __floats2half2_rn(fr.z * scale, fi.z * scale);
            __half2 h3 = __floats2half2_rn(fr.w * scale, fi.w * scale);
            dst[0] = *(unsigned*)&h0;
            dst[1] = *(unsigned*)&h1;
            dst[2] = *(unsigned*)&h2;
            dst[3] = *(unsigned*)&h3;
        }
    }
    __syncthreads();

    Tw tw; make_tw(tw, lane);
#pragma unroll 1
    for (int yr = 0; yr < 4; yr++){
        float2 v[5], o[5];
#pragma unroll
        for (int j = 0; j < 5; j++){
            unsigned u = smw[yr * 1440 + (lane + 32 * j) * 9 + wid];
            v[j] = __half22float2(*(__half2*)&u);
        }
        fft160(v, o, tw, lane);
#pragma unroll
        for (int r2 = 0; r2 < 5; r2++)
            sm1w[wid * 800 + (r2 + 5 * tw.k1) * 5 + yr] =
                __floats2half2_rn(o[r2].x, o[r2].y);
    }
    __syncthreads();

#pragma unroll 1
    for (int i = threadIdx.x; i < 1280; i += 256){
        int d = i / 160;
        int x = i - d * 160;
        const __half2* p = &sm1w[d * 800 + x * 5];
        uint4 val;
        val.x = *(const unsigned*)&p[0];
        val.y = *(const unsigned*)&p[1];
        val.z = *(const unsigned*)&p[2];
        val.w = *(const unsigned*)&p[3];
        *(uint4*)&g_tmp_h[2][k * 8 + d][x][yb * 4] = val;
    }
}

// Pass 2: IDFT along b-axis. grid=(20,16,3), block=256 (8 warps = 8 kd, 8 wk each).
__global__ void __launch_bounds__(256)
pass2_kernel()
{
    int t    = blockIdx.z;
    int kb   = blockIdx.y;
    int wb   = blockIdx.x;
    int wid  = threadIdx.x >> 5;
    int lane = threadIdx.x & 31;
    int kd   = kb * 8 + wid;

    Tw tw; make_tw(tw, lane);

    __shared__ __half2 sm2[GS * 65];  // [h_k]*65 + ww*8 + wid

#pragma unroll 1
    for (int ww = 0; ww < 8; ww++){
        int wk = wb * 8 + ww;
        const __half2* src = &g_tmp_h[t][kd][wk][0];
        float2 v[5], o[5];
#pragma unroll
        for (int j = 0; j < 5; j++)
            v[j] = __half22float2(src[lane + 32 * j]);
        fft160(v, o, tw, lane);
#pragma unroll
        for (int r2 = 0; r2 < 5; r2++)
            sm2[(r2 + 5 * tw.k1) * 65 + ww * 8 + wid] =
                __floats2half2_rn(o[r2].x, o[r2].y);
    }
    __syncthreads();

#pragma unroll 1
    for (int idx = threadIdx.x; idx < GS * 16; idx += 256){
        int h = idx >> 4, rem = idx & 15, ww = rem >> 1, q = rem & 1;
        const __half2* p = &sm2[h * 65 + ww * 8 + q * 4];
        uint4 val;
        val.x = *(const unsigned*)&p[0];
        val.y = *(const unsigned*)&p[1];
        val.z = *(const unsigned*)&p[2];
        val.w = *(const unsigned*)&p[3];
        *(uint4*)&g_field_h[t][h][wb * 8 + ww][kb * 8 + q * 4] = val;
    }
}

// Sample: 16 lanes per point (2 points/warp). Lane sl owns k = sl, all 8 d.
__global__ void __launch_bounds__(256)
sample_kernel(const float* __restrict__ xyz,
              const float* __restrict__ boundp,
              float* __restrict__ out, int npts)
{
    int warp_g = (int)((blockIdx.x * (unsigned)blockDim.x + threadIdx.x) >> 5);
    int lane = threadIdx.x & 31;
    int sub  = lane >> 4;
    int sl   = lane & 15;
    int gw   = warp_g * 2 + sub;
    if (gw >= npts) return;

    float invb = 1.0f / boundp[0];
    float p[3];
    p[0] = xyz[3*gw + 0] * invb;
    p[1] = xyz[3*gw + 1] * invb;
    p[2] = xyz[3*gw + 2] * invb;

    float wa0[3], wa1[3];
    int   c0i[3], c1i[3];
#pragma unroll
    for (int a = 0; a < 3; a++){
        float ia = (p[a] + 1.0f) * 0.5f * 159.0f;
        float fl = floorf(ia);
        float w  = ia - fl;
        int i0 = (int)fl, i1 = i0 + 1;
        float v0 = (i0 >= 0 && i0 <= 159) ? 1.0f : 0.0f;
        float v1 = (i1 >= 0 && i1 <= 159) ? 1.0f : 0.0f;
        c0i[a] = max(0, min(159, i0));
        c1i[a] = max(0, min(159, i1));
        wa0[a] = (1.0f - w) * v0;
        wa1[a] = w * v1;
    }

    const __half2* fld = &g_field_h[0][0][0][0];
    float gacc = 0.0f;

#pragma unroll
    for (int t = 0; t < 3; t++){
        const int ax = (t == 2) ? 0 : 2;    // W axis
        const int ay = (t == 1) ? 0 : 1;    // H axis

        __half2 w00h = __float2half2_rn(wa0[ax] * wa0[ay]);
        __half2 w01h = __float2half2_rn(wa1[ax] * wa0[ay]);
        __half2 w10h = __float2half2_rn(wa0[ax] * wa1[ay]);
        __half2 w11h = __float2half2_rn(wa1[ax] * wa1[ay]);

        int i0 = c0i[ax], i1 = c1i[ax];
        int j0 = c0i[ay], j1 = c1i[ay];

        const __half2* bp = fld + t * GS * GS * KD + sl * 8;
        const uint4* p00 = (const uint4*)(bp + (j0 * GS + i0) * KD);
        const uint4* p01 = (const uint4*)(bp + (j0 * GS + i1) * KD);
        const uint4* p10 = (const uint4*)(bp + (j1 * GS + i0) * KD);
        const uint4* p11 = (const uint4*)(bp + (j1 * GS + i1) * KD);

        float xt = (p[t] + 1.0f) * 0.5f;
        float s1, c1;
        sincospif(2.0f * xt, &s1, &c1);
        float cd[8], sd[8];
        cd[0] = 1.0f; sd[0] = 0.0f;
        float cc = c1, ss = s1;
        cd[1] = 2.0f * cc; sd[1] = 2.0f * ss;
#pragma unroll
        for (int j = 2; j < 8; j++){
            float nc = cc * cc - ss * ss;
            float ns = 2.0f * cc * ss;
            cc = nc; ss = ns;
            cd[j] = 2.0f * cc; sd[j] = 2.0f * ss;
        }

#pragma unroll
        for (int hh = 0; hh < 2; hh++){
            uint4 u00 = p00[hh], u01 = p01[hh], u10 = p10[hh], u11 = p11[hh];
#pragma unroll
            for (int c = 0; c < 4; c++){
                __half2 acc = __hmul2(*(__half2*)&((&u00.x)[c]), w00h);
                acc = __hfma2(*(__half2*)&((&u01.x)[c]), w01h, acc);
                acc = __hfma2(*(__half2*)&((&u10.x)[c]), w10h, acc);
                acc = __hfma2(*(__half2*)&((&u11.x)[c]), w11h, acc);
                float2 f = __half22float2(acc);
                int d = hh * 4 + c;
                gacc += f.x * cd[d] - f.y * sd[d];
            }
        }
    }

    out[gw * NKS + sl] = gacc * INV_FSCALE;
}

extern "C" void kernel_launch(void* const* d_in, const int* in_sizes, int n_in,
                              void* d_out, int out_size)
{
    const float* xyz   = (const float*)d_in[0];
    const float* bound = (const float*)d_in[1];
    const float* alpha = (const float*)d_in[2];
    const float* pur   = (const float*)d_in[3];
    const float* pui   = (const float*)d_in[4];
    const float* pvr   = (const float*)d_in[5];
    const float* pvi   = (const float*)d_in[6];
    const float* pwr   = (const float*)d_in[7];
    const float* pwi   = (const float*)d_in[8];

    dim3 g1(5, 128, 2);
    pass1_t01_kernel<<<g1, 128>>>(pur, pui, pvr, pvi, alpha);

    dim3 gw(40, 16);
    pass1_w_kernel<<<gw, 256>>>(pwr, pwi, alpha);

    dim3 g2(20, 16, 3);
    pass2_kernel<<<g2, 256>>>();

    int npts = in_sizes[0] / 3;
    int nwarps = (npts + 1) / 2;
    int nblocks = (nwarps * 32 + 255) / 256;
    sample_kernel<<<nblocks, 256>>>(xyz, bound, (float*)d_out, npts);
}

// round 8
// speedup vs baseline: 2.3112x; 1.0679x over previous
#include <cuda_runtime.h>
#include <cuda_fp16.h>
#include <math.h>

#define GS   160
#define KD   128
#define NKS  16
#define FSCALE      262144.0f            // 2^18
#define INV_FSCALE  3.814697265625e-06f  // 2^-18

// Intermediates / field in fp16 (values pre-scaled by FSCALE).
__device__ __half2 g_tmp_h[3][KD][GS][GS];     // [t][kd][a_k][b]
__device__ __half2 g_field_h[3][GS][GS][KD];   // [t][h][w][kd]

// ---------------- packed f32x2 helpers (sm_103a) ----------------
typedef unsigned long long u64p;

__device__ __forceinline__ u64p pk2(float x, float y){
    u64p r; asm("mov.b64 %0, {%1, %2};" : "=l"(r) : "f"(x), "f"(y)); return r;
}
__device__ __forceinline__ void upk2(u64p p, float& x, float& y){
    asm("mov.b64 {%0, %1}, %2;" : "=f"(x), "=f"(y) : "l"(p));
}
__device__ __forceinline__ u64p swp2(u64p p){
    float x, y; upk2(p, x, y); return pk2(y, x);
}
__device__ __forceinline__ u64p fma2p(u64p a, u64p b, u64p c){
    u64p d; asm("fma.rn.f32x2 %0, %1, %2, %3;" : "=l"(d) : "l"(a), "l"(b), "l"(c)); return d;
}
__device__ __forceinline__ u64p mul2p(u64p a, u64p b){
    u64p d; asm("mul.rn.f32x2 %0, %1, %2;" : "=l"(d) : "l"(a), "l"(b)); return d;
}
__device__ __forceinline__ u64p add2p(u64p a, u64p b){
    u64p d; asm("add.rn.f32x2 %0, %1, %2;" : "=l"(d) : "l"(a), "l"(b)); return d;
}
// complex mul by twiddle t=(c,s) given tc=(c,c), ts=(-s,s):
// r = (Tx c - Ty s, Ty c + Tx s)
__device__ __forceinline__ u64p cmulp(u64p T, u64p tc, u64p ts){
    return fma2p(swp2(T), ts, mul2p(T, tc));
}

struct Tw {
    u64p stc[5], sts[5], g2[5];   // butterfly stage: (c,c), (-s,s), (g,g)
    u64p tac[4], tas[4];          // ta twiddles r=1..4: (c,c), (-s,s)
    int  k1;                      // brev5(lane)
};

__device__ __forceinline__ float softplus_scale(const float* __restrict__ alpha_params){
    float a0 = alpha_params[0];
    float bx = 10.0f * a0;
    float alpha = (bx > 1.0f) ? a0 : (log1pf(expf(fminf(bx, 1.0f))) * 0.1f);
    return alpha * (1.0f / 25600.0f) * FSCALE;
}

__device__ __forceinline__ void make_tw(Tw &tw, int lane){
#pragma unroll
    for (int s = 0; s < 5; s++){
        int H = 16 >> s;
        float cv = 1.0f, sv = 0.0f, g = 1.0f;
        if (lane & H){
            int j = lane & (H - 1);
            sincospif((float)j / (float)H, &sv, &cv);
            g = -1.0f;
        }
        tw.stc[s] = pk2(cv, cv);
        tw.sts[s] = pk2(-sv, sv);
        tw.g2[s]  = pk2(g, g);
    }
    tw.k1 = (int)(__brev((unsigned)lane) >> 27);
#pragma unroll
    for (int r = 1; r < 5; r++){
        float sv, cv;
        sincospif((float)(lane * r) / 80.0f, &sv, &cv);   // 2pi*lane*r/160
        tw.tac[r - 1] = pk2(cv, cv);
        tw.tas[r - 1] = pk2(-sv, sv);
    }
}

// Inverse-sign DFT-160 across a warp, stride-1 input mapping, packed f32x2.
// Input : lane L, v[j] = x[L + 32*j] packed (re,im)
// Output: o[r]   = X[r + 5*brev5(L)],  X[k] = sum_n x[n] e^{+2pi i nk/160}
__device__ __forceinline__ void fft160p(u64p v[5], u64p o[5], const Tw &tw, int lane){
    const float C1 =  0.30901699437494745f;   // cos(2pi/5)
    const float C2 = -0.80901699437494734f;   // cos(4pi/5)
    const float S1 =  0.95105651629515353f;   // sin(2pi/5)
    const float S2 =  0.58778525229247314f;   // sin(4pi/5)
    const u64p C1p  = pk2(C1, C1),  C2p = pk2(C2, C2);
    const u64p S1p  = pk2(S1, S1),  S2p = pk2(S2, S2);
    const u64p mS1p = pk2(-S1, -S1);
    const u64p NEG1 = pk2(-1.0f, -1.0f);
    const u64p PM   = pk2(-1.0f, 1.0f);
    const u64p MP   = pk2(1.0f, -1.0f);

    // --- symmetric DFT-5 over j ---
    u64p s1 = add2p(v[1], v[4]);
    u64p d1 = fma2p(v[4], NEG1, v[1]);
    u64p s2 = add2p(v[2], v[3]);
    u64p d2 = fma2p(v[3], NEG1, v[2]);
    o[0] = add2p(v[0], add2p(s1, s2));
    u64p ua = fma2p(s2, C2p, fma2p(s1, C1p, v[0]));
    u64p ub = fma2p(s2, C1p, fma2p(s1, C2p, v[0]));
    u64p wa = fma2p(d2, S2p,  mul2p(d1, S1p));
    u64p wb = fma2p(d2, mS1p, mul2p(d1, S2p));
    u64p X1 = fma2p(swp2(wa), PM, ua);    // (uax - way, uay + wax)
    u64p X4 = fma2p(swp2(wa), MP, ua);    // (uax + way, uay - wax)
    u64p X2 = fma2p(swp2(wb), PM, ub);
    u64p X3 = fma2p(swp2(wb), MP, ub);
    o[1] = cmulp(X1, tw.tac[0], tw.tas[0]);
    o[2] = cmulp(X2, tw.tac[1], tw.tas[1]);
    o[3] = cmulp(X3, tw.tac[2], tw.tas[2]);
    o[4] = cmulp(X4, tw.tac[3], tw.tas[3]);

    // --- DFT-32 across lanes (DIF radix-2, sign-folded) ---
#pragma unroll
    for (int s = 0; s < 5; s++){
        int H = 16 >> s;
#pragma unroll
        for (int r = 0; r < 5; r++){
            float ox, oy; upk2(o[r], ox, oy);
            float px = __shfl_xor_sync(0xffffffffu, ox, H);
            float py = __shfl_xor_sync(0xffffffffu, oy, H);
            u64p T = fma2p(o[r], tw.g2[s], pk2(px, py));
            o[r] = cmulp(T, tw.stc[s], tw.sts[s]);
        }
    }
}

// Merged pass 1: grid (40, 16, 3), 256 threads.
//  z = 0 : Pu,  z = 1 : Pv  (contiguous-axis loads; block = 32 rows of one kd)
//  z = 2 : Pw  (smem-staged coalesced float4 loads; block = (k, 4 Y rows, 8 d))
__global__ void __launch_bounds__(256)
pass1_all_kernel(const float* __restrict__ pur, const float* __restrict__ pui,
                 const float* __restrict__ pvr, const float* __restrict__ pvi,
                 const float* __restrict__ pwr, const float* __restrict__ pwi,
                 const float* __restrict__ alpha_params)
{
    __shared__ char smbuf[48640];
    int z    = blockIdx.z;
    int wid  = threadIdx.x >> 5;
    int lane = threadIdx.x & 31;
    float scale = softplus_scale(alpha_params);

    if (z < 2){
        // ---- t01 path ----
        int id = blockIdx.x + 40 * blockIdx.y;   // 0..639
        int kd = id / 5;
        int bx = id - kd * 5;                    // row-block 0..4
        const float* re = (z == 0) ? pur : pvr;
        const float* im = (z == 0) ? pui : pvi;
        int k = kd >> 3, d = kd & 7;

        Tw tw; make_tw(tw, lane);
        __half2* sm1 = (__half2*)smbuf;          // [a_k]*33 + rowlocal(0..31)

#pragma unroll 1
        for (int r = 0; r < 4; r++){
            int rl = wid * 4 + r;
            int b  = bx * 32 + rl;
            int base = (z == 0) ? ((kd * GS + b) * GS)
                                : (((k * GS + b) * 8 + d) * GS);
            u64p v[5], o[5];
#pragma unroll
            for (int j = 0; j < 5; j++){
                int idx = base + lane + 32 * j;
                v[j] = pk2(re[idx] * scale, im[idx] * scale);
            }
            fft160p(v, o, tw, lane);
#pragma unroll
            for (int r2 = 0; r2 < 5; r2++){
                float x, y; upk2(o[r2], x, y);
                sm1[(r2 + 5 * tw.k1) * 33 + rl] = __floats2half2_rn(x, y);
            }
        }
        __syncthreads();

#pragma unroll 1
        for (int idx = threadIdx.x; idx < GS * 8; idx += 256){
            int w = idx >> 3, g = idx & 7;
            const __half2* p = &sm1[w * 33 + g * 4];
            uint4 val;
            val.x = *(const unsigned*)&p[0];
            val.y = *(const unsigned*)&p[1];
            val.z = *(const unsigned*)&p[2];
            val.w = *(const unsigned*)&p[3];
            *(uint4*)&g_tmp_h[z][kd][w][bx * 32 + g * 4] = val;
        }
    } else {
        // ---- Pw path ----
        int id = blockIdx.x + 40 * blockIdx.y;   // 0..639
        int k  = id / 40;                         // 0..15
        int yb = id - k * 40;                     // 0..39 (4 Y rows each)

        unsigned* smw  = (unsigned*)smbuf;                    // [y][X*9 + d] (pad 9): 4*1440
        __half2*  sm1w = (__half2*)(smbuf + 4 * 1440 * 4);    // [d][x_k*5 + y]: 8*800

        {
            const float4* re4 = (const float4*)pwr;
            const float4* im4 = (const float4*)pwi;
            int y0 = yb * 4;
#pragma unroll 1
            for (int i = threadIdx.x; i < 1280; i += 256){
                int X   = i >> 3;
                int rem = i & 7;
                int y   = rem >> 1;
                int dg  = (rem & 1) * 4;
                int gidx = ((k * GS + X) * GS + y0 + y) * 2 + (rem & 1);
                float4 fr = re4[gidx];
                float4 fi = im4[gidx];
                unsigned* dst = &smw[y * 1440 + X * 9 + dg];
                __half2 h0 = __floats2half2_rn(fr.x * scale, fi.x * scale);
                __half2 h1 = __floats2half2_rn(fr.y * scale, fi.y * scale);
                __half2 h2 = __floats2half2_rn(fr.z * scale, fi.z * scale);
                __half2 h3 = __floats2half2_rn(fr.w * scale, fi.w * scale);
                dst[0] = *(unsigned*)&h0;
                dst[1] = *(unsigned*)&h1;
                dst[2] = *(unsigned*)&h2;
                dst[3] = *(unsigned*)&h3;
            }
        }
        __syncthreads();

        Tw tw; make_tw(tw, lane);
#pragma unroll 1
        for (int yr = 0; yr < 4; yr++){
            u64p v[5], o[5];
#pragma unroll
            for (int j = 0; j < 5; j++){
                unsigned u = smw[yr * 1440 + (lane + 32 * j) * 9 + wid];
                float2 f = __half22float2(*(__half2*)&u);
                v[j] = pk2(f.x, f.y);
            }
            fft160p(v, o, tw, lane);
#pragma unroll
            for (int r2 = 0; r2 < 5; r2++){
                float x, y; upk2(o[r2], x, y);
                sm1w[wid * 800 + (r2 + 5 * tw.k1) * 5 + yr] = __floats2half2_rn(x, y);
            }
        }
        __syncthreads();

#pragma unroll 1
        for (int i = threadIdx.x; i < 1280; i += 256){
            int d = i / 160;
            int x = i - d * 160;
            const __half2* p = &sm1w[d * 800 + x * 5];
            uint4 val;
            val.x = *(const unsigned*)&p[0];
            val.y = *(const unsigned*)&p[1];
            val.z = *(const unsigned*)&p[2];
            val.w = *(const unsigned*)&p[3];
            *(uint4*)&g_tmp_h[2][k * 8 + d][x][yb * 4] = val;
        }
    }
}

// Pass 2: IDFT along b-axis. grid=(20,16,3), block=256 (8 warps = 8 kd, 8 wk each).
__global__ void __launch_bounds__(256)
pass2_kernel()
{
    int t    = blockIdx.z;
    int kb   = blockIdx.y;
    int wb   = blockIdx.x;
    int wid  = threadIdx.x >> 5;
    int lane = threadIdx.x & 31;
    int kd   = kb * 8 + wid;

    Tw tw; make_tw(tw, lane);

    __shared__ __half2 sm2[GS * 65];  // [h_k]*65 + ww*8 + wid

#pragma unroll 1
    for (int ww = 0; ww < 8; ww++){
        int wk = wb * 8 + ww;
        const __half2* src = &g_tmp_h[t][kd][wk][0];
        u64p v[5], o[5];
#pragma unroll
        for (int j = 0; j < 5; j++){
            float2 f = __half22float2(src[lane + 32 * j]);
            v[j] = pk2(f.x, f.y);
        }
        fft160p(v, o, tw, lane);
#pragma unroll
        for (int r2 = 0; r2 < 5; r2++){
            float x, y; upk2(o[r2], x, y);
            sm2[(r2 + 5 * tw.k1) * 65 + ww * 8 + wid] = __floats2half2_rn(x, y);
        }
    }
    __syncthreads();

#pragma unroll 1
    for (int idx = threadIdx.x; idx < GS * 16; idx += 256){
        int h = idx >> 4, rem = idx & 15, ww = rem >> 1, q = rem & 1;
        const __half2* p = &sm2[h * 65 + ww * 8 + q * 4];
        uint4 val;
        val.x = *(const unsigned*)&p[0];
        val.y = *(const unsigned*)&p[1];
        val.z = *(const unsigned*)&p[2];
        val.w = *(const unsigned*)&p[3];
        *(uint4*)&g_field_h[t][h][wb * 8 + ww][kb * 8 + q * 4] = val;
    }
}

// Sample: 16 lanes per point (2 points/warp). Lane sl owns k = sl, all 8 d.
__global__ void __launch_bounds__(256)
sample_kernel(const float* __restrict__ xyz,
              const float* __restrict__ boundp,
              float* __restrict__ out, int npts)
{
    int warp_g = (int)((blockIdx.x * (unsigned)blockDim.x + threadIdx.x) >> 5);
    int lane = threadIdx.x & 31;
    int sub  = lane >> 4;
    int sl   = lane & 15;
    int gw   = warp_g * 2 + sub;
    if (gw >= npts) return;

    float invb = 1.0f / boundp[0];
    float p[3];
    p[0] = xyz[3*gw + 0] * invb;
    p[1] = xyz[3*gw + 1] * invb;
    p[2] = xyz[3*gw + 2] * invb;

    float wa0[3], wa1[3];
    int   c0i[3], c1i[3];
#pragma unroll
    for (int a = 0; a < 3; a++){
        float ia = (p[a] + 1.0f) * 0.5f * 159.0f;
        float fl = floorf(ia);
        float w  = ia - fl;
        int i0 = (int)fl, i1 = i0 + 1;
        float v0 = (i0 >= 0 && i0 <= 159) ? 1.0f : 0.0f;
        float v1 = (i1 >= 0 && i1 <= 159) ? 1.0f : 0.0f;
        c0i[a] = max(0, min(159, i0));
        c1i[a] = max(0, min(159, i1));
        wa0[a] = (1.0f - w) * v0;
        wa1[a] = w * v1;
    }

    const __half2* fld = &g_field_h[0][0][0][0];
    float gacc = 0.0f;

#pragma unroll
    for (int t = 0; t < 3; t++){
        const int ax = (t == 2) ? 0 : 2;    // W axis
        const int ay = (t == 1) ? 0 : 1;    // H axis

        __half2 w00h = __float2half2_rn(wa0[ax] * wa0[ay]);
        __half2 w01h = __float2half2_rn(wa1[ax] * wa0[ay]);
        __half2 w10h = __float2half2_rn(wa0[ax] * wa1[ay]);
        __half2 w11h = __float2half2_rn(wa1[ax] * wa1[ay]);

        int i0 = c0i[ax], i1 = c1i[ax];
        int j0 = c0i[ay], j1 = c1i[ay];

        const __half2* bp = fld + t * GS * GS * KD + sl * 8;
        const uint4* p00 = (const uint4*)(bp + (j0 * GS + i0) * KD);
        const uint4* p01 = (const uint4*)(bp + (j0 * GS + i1) * KD);
        const uint4* p10 = (const uint4*)(bp + (j1 * GS + i0) * KD);
        const uint4* p11 = (const uint4*)(bp + (j1 * GS + i1) * KD);

        float xt = (p[t] + 1.0f) * 0.5f;
        float s1, c1;
        sincospif(2.0f * xt, &s1, &c1);
        float cd[8], sd[8];
        cd[0] = 1.0f; sd[0] = 0.0f;
        float cc = c1, ss = s1;
        cd[1] = 2.0f * cc; sd[1] = 2.0f * ss;
#pragma unroll
        for (int j = 2; j < 8; j++){
            float nc = cc * cc - ss * ss;
            float ns = 2.0f * cc * ss;
            cc = nc; ss = ns;
            cd[j] = 2.0f * cc; sd[j] = 2.0f * ss;
        }

#pragma unroll
        for (int hh = 0; hh < 2; hh++){
            uint4 u00 = p00[hh], u01 = p01[hh], u10 = p10[hh], u11 = p11[hh];
#pragma unroll
            for (int c = 0; c < 4; c++){
                __half2 acc = __hmul2(*(__half2*)&((&u00.x)[c]), w00h);
                acc = __hfma2(*(__half2*)&((&u01.x)[c]), w01h, acc);
                acc = __hfma2(*(__half2*)&((&u10.x)[c]), w10h, acc);
                acc = __hfma2(*(__half2*)&((&u11.x)[c]), w11h, acc);
                float2 f = __half22float2(acc);
                int d = hh * 4 + c;
                gacc += f.x * cd[d] - f.y * sd[d];
            }
        }
    }

    out[gw * NKS + sl] = gacc * INV_FSCALE;
}

extern "C" void kernel_launch(void* const* d_in, const int* in_sizes, int n_in,
                              void* d_out, int out_size)
{
    const float* xyz   = (const float*)d_in[0];
    const float* bound = (const float*)d_in[1];
    const float* alpha = (const float*)d_in[2];
    const float* pur   = (const float*)d_in[3];
    const float* pui   = (const float*)d_in[4];
    const float* pvr   = (const float*)d_in[5];
    const float* pvi   = (const float*)d_in[6];
    const float* pwr   = (const float*)d_in[7];
    const float* pwi   = (const float*)d_in[8];

    dim3 g1(40, 16, 3);
    pass1_all_kernel<<<g1, 256>>>(pur, pui, pvr, pvi, pwr, pwi, alpha);

    dim3 g2(20, 16, 3);
    pass2_kernel<<<g2, 256>>>();

    int npts = in_sizes[0] / 3;
    int nwarps = (npts + 1) / 2;
    int nblocks = (nwarps * 32 + 255) / 256;
    sample_kernel<<<nblocks, 256>>>(xyz, bound, (float*)d_out, npts);
}

// round 9
// speedup vs baseline: 2.3381x; 1.0116x over previous
#include <cuda_runtime.h>
#include <cuda_fp16.h>
#include <math.h>

#define GS   160
#define KD   128
#define NKS  16
#define FSCALE      262144.0f            // 2^18
#define INV_FSCALE  3.814697265625e-06f  // 2^-18

__device__ __half2 g_tmp_h[3][KD][GS][GS];     // [t][kd][a_k][b]
__device__ __half2 g_field_h[3][GS][GS][KD];   // [t][h][w][kd]

// ---------------- packed f32x2 helpers (sm_103a) ----------------
typedef unsigned long long u64p;

__device__ __forceinline__ u64p pk2(float x, float y){
    u64p r; asm("mov.b64 %0, {%1, %2};" : "=l"(r) : "f"(x), "f"(y)); return r;
}
__device__ __forceinline__ void upk2(u64p p, float& x, float& y){
    asm("mov.b64 {%0, %1}, %2;" : "=f"(x), "=f"(y) : "l"(p));
}
__device__ __forceinline__ u64p swp2(u64p p){
    float x, y; upk2(p, x, y); return pk2(y, x);
}
__device__ __forceinline__ u64p fma2p(u64p a, u64p b, u64p c){
    u64p d; asm("fma.rn.f32x2 %0, %1, %2, %3;" : "=l"(d) : "l"(a), "l"(b), "l"(c)); return d;
}
__device__ __forceinline__ u64p mul2p(u64p a, u64p b){
    u64p d; asm("mul.rn.f32x2 %0, %1, %2;" : "=l"(d) : "l"(a), "l"(b)); return d;
}
__device__ __forceinline__ u64p add2p(u64p a, u64p b){
    u64p d; asm("add.rn.f32x2 %0, %1, %2;" : "=l"(d) : "l"(a), "l"(b)); return d;
}
__device__ __forceinline__ u64p cmulp(u64p T, u64p tc, u64p ts){
    return fma2p(swp2(T), ts, mul2p(T, tc));
}

struct Tw {
    u64p stc[5], sts[5], g2[5];
    u64p tac[4], tas[4];
    int  k1;
};

__device__ __forceinline__ float softplus_scale(const float* __restrict__ alpha_params){
    float a0 = alpha_params[0];
    float bx = 10.0f * a0;
    float alpha = (bx > 1.0f) ? a0 : (log1pf(expf(fminf(bx, 1.0f))) * 0.1f);
    return alpha * (1.0f / 25600.0f) * FSCALE;
}

__device__ __forceinline__ void make_tw(Tw &tw, int lane){
#pragma unroll
    for (int s = 0; s < 5; s++){
        int H = 16 >> s;
        float cv = 1.0f, sv = 0.0f, g = 1.0f;
        if (lane & H){
            int j = lane & (H - 1);
            sincospif((float)j / (float)H, &sv, &cv);
            g = -1.0f;
        }
        tw.stc[s] = pk2(cv, cv);
        tw.sts[s] = pk2(-sv, sv);
        tw.g2[s]  = pk2(g, g);
    }
    tw.k1 = (int)(__brev((unsigned)lane) >> 27);
#pragma unroll
    for (int r = 1; r < 5; r++){
        float sv, cv;
        sincospif((float)(lane * r) / 80.0f, &sv, &cv);
        tw.tac[r - 1] = pk2(cv, cv);
        tw.tas[r - 1] = pk2(-sv, sv);
    }
}

// Inverse-sign DFT-160 across a warp, stride-1 input mapping, packed f32x2.
__device__ __forceinline__ void fft160p(u64p v[5], u64p o[5], const Tw &tw, int lane){
    const float C1 =  0.30901699437494745f;
    const float C2 = -0.80901699437494734f;
    const float S1 =  0.95105651629515353f;
    const float S2 =  0.58778525229247314f;
    const u64p C1p  = pk2(C1, C1),  C2p = pk2(C2, C2);
    const u64p S1p  = pk2(S1, S1),  S2p = pk2(S2, S2);
    const u64p mS1p = pk2(-S1, -S1);
    const u64p NEG1 = pk2(-1.0f, -1.0f);
    const u64p PM   = pk2(-1.0f, 1.0f);
    const u64p MP   = pk2(1.0f, -1.0f);

    u64p s1 = add2p(v[1], v[4]);
    u64p d1 = fma2p(v[4], NEG1, v[1]);
    u64p s2 = add2p(v[2], v[3]);
    u64p d2 = fma2p(v[3], NEG1, v[2]);
    o[0] = add2p(v[0], add2p(s1, s2));
    u64p ua = fma2p(s2, C2p, fma2p(s1, C1p, v[0]));
    u64p ub = fma2p(s2, C1p, fma2p(s1, C2p, v[0]));
    u64p wa = fma2p(d2, S2p,  mul2p(d1, S1p));
    u64p wb = fma2p(d2, mS1p, mul2p(d1, S2p));
    u64p X1 = fma2p(swp2(wa), PM, ua);
    u64p X4 = fma2p(swp2(wa), MP, ua);
    u64p X2 = fma2p(swp2(wb), PM, ub);
    u64p X3 = fma2p(swp2(wb), MP, ub);
    o[1] = cmulp(X1, tw.tac[0], tw.tas[0]);
    o[2] = cmulp(X2, tw.tac[1], tw.tas[1]);
    o[3] = cmulp(X3, tw.tac[2], tw.tas[2]);
    o[4] = cmulp(X4, tw.tac[3], tw.tas[3]);

#pragma unroll
    for (int s = 0; s < 5; s++){
        int H = 16 >> s;
#pragma unroll
        for (int r = 0; r < 5; r++){
            float ox, oy; upk2(o[r], ox, oy);
            float px = __shfl_xor_sync(0xffffffffu, ox, H);
            float py = __shfl_xor_sync(0xffffffffu, oy, H);
            u64p T = fma2p(o[r], tw.g2[s], pk2(px, py));
            o[r] = cmulp(T, tw.stc[s], tw.sts[s]);
        }
    }
}

// Merged pass 1: grid (40, 16, 3), 256 threads.
__global__ void __launch_bounds__(256)
pass1_all_kernel(const float* __restrict__ pur, const float* __restrict__ pui,
                 const float* __restrict__ pvr, const float* __restrict__ pvi,
                 const float* __restrict__ pwr, const float* __restrict__ pwi,
                 const float* __restrict__ alpha_params)
{
    __shared__ char smbuf[48640];
    int z    = blockIdx.z;
    int wid  = threadIdx.x >> 5;
    int lane = threadIdx.x & 31;
    float scale = softplus_scale(alpha_params);

    if (z < 2){
        int id = blockIdx.x + 40 * blockIdx.y;
        int kd = id / 5;
        int bx = id - kd * 5;
        const float* re = (z == 0) ? pur : pvr;
        const float* im = (z == 0) ? pui : pvi;
        int k = kd >> 3, d = kd & 7;

        Tw tw; make_tw(tw, lane);
        __half2* sm1 = (__half2*)smbuf;

        // prefetch row 0
        u64p v[5];
        {
            int b0 = bx * 32 + wid * 4;
            int base = (z == 0) ? ((kd * GS + b0) * GS)
                                : (((k * GS + b0) * 8 + d) * GS);
#pragma unroll
            for (int j = 0; j < 5; j++){
                int idx = base + lane + 32 * j;
                v[j] = pk2(re[idx] * scale, im[idx] * scale);
            }
        }
#pragma unroll 1
        for (int r = 0; r < 4; r++){
            u64p cur[5];
#pragma unroll
            for (int j = 0; j < 5; j++) cur[j] = v[j];
            if (r < 3){
                int b = bx * 32 + wid * 4 + r + 1;
                int base = (z == 0) ? ((kd * GS + b) * GS)
                                    : (((k * GS + b) * 8 + d) * GS);
#pragma unroll
                for (int j = 0; j < 5; j++){
                    int idx = base + lane + 32 * j;
                    v[j] = pk2(re[idx] * scale, im[idx] * scale);
                }
            }
            u64p o[5];
            fft160p(cur, o, tw, lane);
            int rl = wid * 4 + r;
#pragma unroll
            for (int r2 = 0; r2 < 5; r2++){
                float x, y; upk2(o[r2], x, y);
                sm1[(r2 + 5 * tw.k1) * 33 + rl] = __floats2half2_rn(x, y);
            }
        }
        __syncthreads();

#pragma unroll 1
        for (int idx = threadIdx.x; idx < GS * 8; idx += 256){
            int w = idx >> 3, g = idx & 7;
            const __half2* p = &sm1[w * 33 + g * 4];
            uint4 val;
            val.x = *(const unsigned*)&p[0];
            val.y = *(const unsigned*)&p[1];
            val.z = *(const unsigned*)&p[2];
            val.w = *(const unsigned*)&p[3];
            *(uint4*)&g_tmp_h[z][kd][w][bx * 32 + g * 4] = val;
        }
    } else {
        int id = blockIdx.x + 40 * blockIdx.y;
        int k  = id / 40;
        int yb = id - k * 40;

        unsigned* smw  = (unsigned*)smbuf;                 // [y][X*9 + d] (pad 9)
        __half2*  sm1w = (__half2*)(smbuf + 4 * 1440 * 4); // [d][x_k*5 + y]

        {
            const float4* re4 = (const float4*)pwr;
            const float4* im4 = (const float4*)pwi;
            int y0 = yb * 4;
#pragma unroll 1
            for (int i = threadIdx.x; i < 1280; i += 256){
                int X   = i >> 3;
                int rem = i & 7;
                int y   = rem >> 1;
                int dg  = (rem & 1) * 4;
                int gidx = ((k * GS + X) * GS + y0 + y) * 2 + (rem & 1);
                float4 fr = re4[gidx];
                float4 fi = im4[gidx];
                unsigned* dst = &smw[y * 1440 + X * 9 + dg];
                __half2 h0 = __floats2half2_rn(fr.x * scale, fi.x * scale);
                __half2 h1 = __floats2half2_rn(fr.y * scale, fi.y * scale);
                __half2 h2 = __floats2half2_rn(fr.z * scale, fi.z * scale);
                __half2 h3 = __floats2half2_rn(fr.w * scale, fi.w * scale);
                dst[0] = *(unsigned*)&h0;
                dst[1] = *(unsigned*)&h1;
                dst[2] = *(unsigned*)&h2;
                dst[3] = *(unsigned*)&h3;
            }
        }
        __syncthreads();

        Tw tw; make_tw(tw, lane);
#pragma unroll 1
        for (int yr = 0; yr < 4; yr++){
            u64p v[5], o[5];
#pragma unroll
            for (int j = 0; j < 5; j++){
                unsigned u = smw[yr * 1440 + (lane + 32 * j) * 9 + wid];
                float2 f = __half22float2(*(__half2*)&u);
                v[j] = pk2(f.x, f.y);
            }
            fft160p(v, o, tw, lane);
#pragma unroll
            for (int r2 = 0; r2 < 5; r2++){
                float x, y; upk2(o[r2], x, y);
                sm1w[wid * 800 + (r2 + 5 * tw.k1) * 5 + yr] = __floats2half2_rn(x, y);
            }
        }
        __syncthreads();

#pragma unroll 1
        for (int i = threadIdx.x; i < 1280; i += 256){
            int d = i / 160;
            int x = i - d * 160;
            const __half2* p = &sm1w[d * 800 + x * 5];
            uint4 val;
            val.x = *(const unsigned*)&p[0];
            val.y = *(const unsigned*)&p[1];
            val.z = *(const unsigned*)&p[2];
            val.w = *(const unsigned*)&p[3];
            *(uint4*)&g_tmp_h[2][k * 8 + d][x][yb * 4] = val;
        }
    }
}

// Pass 2: IDFT along b-axis. grid=(20,16,3), block=256 (8 warps = 8 kd, 8 wk each).
__global__ void __launch_bounds__(256)
pass2_kernel()
{
    int t    = blockIdx.z;
    int kb   = blockIdx.y;
    int wb   = blockIdx.x;
    int wid  = threadIdx.x >> 5;
    int lane = threadIdx.x & 31;
    int kd   = kb * 8 + wid;

    Tw tw; make_tw(tw, lane);

    __shared__ __half2 sm2[GS * 65];

    // prefetch ww = 0
    u64p v[5];
    {
        const __half2* src = &g_tmp_h[t][kd][wb * 8][0];
#pragma unroll
        for (int j = 0; j < 5; j++){
            float2 f = __half22float2(src[lane + 32 * j]);
            v[j] = pk2(f.x, f.y);
        }
    }
#pragma unroll 1
    for (int ww = 0; ww < 8; ww++){
        u64p cur[5];
#pragma unroll
        for (int j = 0; j < 5; j++) cur[j] = v[j];
        if (ww < 7){
            const __half2* src = &g_tmp_h[t][kd][wb * 8 + ww + 1][0];
#pragma unroll
            for (int j = 0; j < 5; j++){
                float2 f = __half22float2(src[lane + 32 * j]);
                v[j] = pk2(f.x, f.y);
            }
        }
        u64p o[5];
        fft160p(cur, o, tw, lane);
#pragma unroll
        for (int r2 = 0; r2 < 5; r2++){
            float x, y; upk2(o[r2], x, y);
            sm2[(r2 + 5 * tw.k1) * 65 + ww * 8 + wid] = __floats2half2_rn(x, y);
        }
    }
    __syncthreads();

#pragma unroll 1
    for (int idx = threadIdx.x; idx < GS * 16; idx += 256){
        int h = idx >> 4, rem = idx & 15, ww = rem >> 1, q = rem & 1;
        const __half2* p = &sm2[h * 65 + ww * 8 + q * 4];
        uint4 val;
        val.x = *(const unsigned*)&p[0];
        val.y = *(const unsigned*)&p[1];
        val.z = *(const unsigned*)&p[2];
        val.w = *(const unsigned*)&p[3];
        *(uint4*)&g_field_h[t][h][wb * 8 + ww][kb * 8 + q * 4] = val;
    }
}

// Sample: 16 lanes per point (2 points/warp), DENSE cell loads.
// Cell = 512 B = 32 uint4. Lane sl reads uint4 #sl (kd 4sl..4sl+3) and
// uint4 #(16+sl) (kd 64+4sl..). So lane sl holds k = sl>>1 (group 0) and
// k = 8+(sl>>1) (group 1), d-range (sl&1)*4..+3 in both.
__global__ void __launch_bounds__(256)
sample_kernel(const float* __restrict__ xyz,
              const float* __restrict__ boundp,
              float* __restrict__ out, int npts)
{
    int warp_g = (int)((blockIdx.x * (unsigned)blockDim.x + threadIdx.x) >> 5);
    int lane = threadIdx.x & 31;
    int sub  = lane >> 4;
    int sl   = lane & 15;
    int gw   = warp_g * 2 + sub;
    if (gw >= npts) return;

    float invb = 1.0f / boundp[0];
    float p[3];
    p[0] = xyz[3*gw + 0] * invb;
    p[1] = xyz[3*gw + 1] * invb;
    p[2] = xyz[3*gw + 2] * invb;

    float wa0[3], wa1[3];
    int   c0i[3], c1i[3];
#pragma unroll
    for (int a = 0; a < 3; a++){
        float ia = (p[a] + 1.0f) * 0.5f * 159.0f;
        float fl = floorf(ia);
        float w  = ia - fl;
        int i0 = (int)fl, i1 = i0 + 1;
        float v0 = (i0 >= 0 && i0 <= 159) ? 1.0f : 0.0f;
        float v1 = (i1 >= 0 && i1 <= 159) ? 1.0f : 0.0f;
        c0i[a] = max(0, min(159, i0));
        c1i[a] = max(0, min(159, i1));
        wa0[a] = (1.0f - w) * v0;
        wa1[a] = w * v1;
    }

    const __half2* fld = &g_field_h[0][0][0][0];
    bool hi = (sl & 1) != 0;
    float gacc0 = 0.0f, gacc1 = 0.0f;

#pragma unroll
    for (int t = 0; t < 3; t++){
        const int ax = (t == 2) ? 0 : 2;    // W axis
        const int ay = (t == 1) ? 0 : 1;    // H axis

        __half2 w00h = __float2half2_rn(wa0[ax] * wa0[ay]);
        __half2 w01h = __float2half2_rn(wa1[ax] * wa0[ay]);
        __half2 w10h = __float2half2_rn(wa0[ax] * wa1[ay]);
        __half2 w11h = __float2half2_rn(wa1[ax] * wa1[ay]);

        int i0 = c0i[ax], i1 = c1i[ax];
        int j0 = c0i[ay], j1 = c1i[ay];

        const __half2* bp = fld + t * GS * GS * KD;
        const uint4* q00 = (const uint4*)(bp + (j0 * GS + i0) * KD) + sl;
        const uint4* q01 = (const uint4*)(bp + (j0 * GS + i1) * KD) + sl;
        const uint4* q10 = (const uint4*)(bp + (j1 * GS + i0) * KD) + sl;
        const uint4* q11 = (const uint4*)(bp + (j1 * GS + i1) * KD) + sl;

        float xt = (p[t] + 1.0f) * 0.5f;
        float s1, c1;
        sincospif(2.0f * xt, &s1, &c1);
        float cd[8], sd[8];
        cd[0] = 1.0f; sd[0] = 0.0f;
        float cc = c1, ss = s1;
        cd[1] = 2.0f * cc; sd[1] = 2.0f * ss;
#pragma unroll
        for (int j = 2; j < 8; j++){
            float nc = cc * cc - ss * ss;
            float ns = 2.0f * cc * ss;
            cc = nc; ss = ns;
            cd[j] = 2.0f * cc; sd[j] = 2.0f * ss;
        }
        // lane's d-range weights: d = (sl&1)*4 + c
        float cs0 = hi ? cd[4] : cd[0], ss0 = hi ? sd[4] : sd[0];
        float cs1 = hi ? cd[5] : cd[1], ss1 = hi ? sd[5] : sd[1];
        float cs2 = hi ? cd[6] : cd[2], ss2 = hi ? sd[6] : sd[2];
        float cs3 = hi ? cd[7] : cd[3], ss3 = hi ? sd[7] : sd[3];

#pragma unroll
        for (int g = 0; g < 2; g++){
            uint4 u00 = q00[g * 16], u01 = q01[g * 16];
            uint4 u10 = q10[g * 16], u11 = q11[g * 16];
            float acc_s = 0.0f;
#pragma unroll
            for (int c = 0; c < 4; c++){
                __half2 acc = __hmul2(*(__half2*)&((&u00.x)[c]), w00h);
                acc = __hfma2(*(__half2*)&((&u01.x)[c]), w01h, acc);
                acc = __hfma2(*(__half2*)&((&u10.x)[c]), w10h, acc);
                acc = __hfma2(*(__half2*)&((&u11.x)[c]), w11h, acc);
                float2 f = __half22float2(acc);
                float csv = (c == 0) ? cs0 : (c == 1) ? cs1 : (c == 2) ? cs2 : cs3;
                float ssv = (c == 0) ? ss0 : (c == 1) ? ss1 : (c == 2) ? ss2 : ss3;
                acc_s += f.x * csv - f.y * ssv;
            }
            if (g == 0) gacc0 += acc_s; else gacc1 += acc_s;
        }
    }

    // pair-reduce: lanes sl and sl^1 hold the two d-halves of the same k's
    gacc0 += __shfl_xor_sync(0xffffffffu, gacc0, 1);
    gacc1 += __shfl_xor_sync(0xffffffffu, gacc1, 1);
    int  kout = hi ? (8 + (sl >> 1)) : (sl >> 1);
    float val = (hi ? gacc1 : gacc0) * INV_FSCALE;
    out[gw * NKS + kout] = val;
}

extern "C" void kernel_launch(void* const* d_in, const int* in_sizes, int n_in,
                              void* d_out, int out_size)
{
    const float* xyz   = (const float*)d_in[0];
    const float* bound = (const float*)d_in[1];
    const float* alpha = (const float*)d_in[2];
    const float* pur   = (const float*)d_in[3];
    const float* pui   = (const float*)d_in[4];
    const float* pvr   = (const float*)d_in[5];
    const float* pvi   = (const float*)d_in[6];
    const float* pwr   = (const float*)d_in[7];
    const float* pwi   = (const float*)d_in[8];

    dim3 g1(40, 16, 3);
    pass1_all_kernel<<<g1, 256>>>(pur, pui, pvr, pvi, pwr, pwi, alpha);

    dim3 g2(20, 16, 3);
    pass2_kernel<<<g2, 256>>>();

    int npts = in_sizes[0] / 3;
    int nwarps = (npts + 1) / 2;
    int nblocks = (nwarps * 32 + 255) / 256;
    sample_kernel<<<nblocks, 256>>>(xyz, bound, (float*)d_out, npts);
}

// round 10
// speedup vs baseline: 2.4727x; 1.0576x over previous
#include <cuda_runtime.h>
#include <cuda_fp16.h>
#include <math.h>

#define GS   160
#define KD   128
#define NKS  16
#define FSCALE      262144.0f            // 2^18
#define INV_FSCALE  3.814697265625e-06f  // 2^-18

#define SPEC_GRID 608                    // 4 blocks/SM x 152 SMs (GB300)

__device__ __half2 g_tmp_h[3][KD][GS][GS];     // [t][kd][a_k][b]
__device__ __half2 g_field_h[3][GS][GS][KD];   // [t][h][w][kd]

// ---------------- packed f32x2 helpers (sm_103a) ----------------
typedef unsigned long long u64p;

__device__ __forceinline__ u64p pk2(float x, float y){
    u64p r; asm("mov.b64 %0, {%1, %2};" : "=l"(r) : "f"(x), "f"(y)); return r;
}
__device__ __forceinline__ void upk2(u64p p, float& x, float& y){
    asm("mov.b64 {%0, %1}, %2;" : "=f"(x), "=f"(y) : "l"(p));
}
__device__ __forceinline__ u64p swp2(u64p p){
    float x, y; upk2(p, x, y); return pk2(y, x);
}
__device__ __forceinline__ u64p fma2p(u64p a, u64p b, u64p c){
    u64p d; asm("fma.rn.f32x2 %0, %1, %2, %3;" : "=l"(d) : "l"(a), "l"(b), "l"(c)); return d;
}
__device__ __forceinline__ u64p mul2p(u64p a, u64p b){
    u64p d; asm("mul.rn.f32x2 %0, %1, %2;" : "=l"(d) : "l"(a), "l"(b)); return d;
}
__device__ __forceinline__ u64p add2p(u64p a, u64p b){
    u64p d; asm("add.rn.f32x2 %0, %1, %2;" : "=l"(d) : "l"(a), "l"(b)); return d;
}
__device__ __forceinline__ u64p cmulp(u64p T, u64p tc, u64p ts){
    return fma2p(swp2(T), ts, mul2p(T, tc));
}

struct Tw {
    u64p stc[5], sts[5], g2[5];
    u64p tac[4], tas[4];
    int  k1;
};

__device__ __forceinline__ float softplus_scale(const float* __restrict__ alpha_params){
    float a0 = alpha_params[0];
    float bx = 10.0f * a0;
    float alpha = (bx > 1.0f) ? a0 : (log1pf(expf(fminf(bx, 1.0f))) * 0.1f);
    return alpha * (1.0f / 25600.0f) * FSCALE;
}

__device__ __forceinline__ void make_tw(Tw &tw, int lane){
#pragma unroll
    for (int s = 0; s < 5; s++){
        int H = 16 >> s;
        float cv = 1.0f, sv = 0.0f, g = 1.0f;
        if (lane & H){
            int j = lane & (H - 1);
            sincospif((float)j / (float)H, &sv, &cv);
            g = -1.0f;
        }
        tw.stc[s] = pk2(cv, cv);
        tw.sts[s] = pk2(-sv, sv);
        tw.g2[s]  = pk2(g, g);
    }
    tw.k1 = (int)(__brev((unsigned)lane) >> 27);
#pragma unroll
    for (int r = 1; r < 5; r++){
        float sv, cv;
        sincospif((float)(lane * r) / 80.0f, &sv, &cv);
        tw.tac[r - 1] = pk2(cv, cv);
        tw.tas[r - 1] = pk2(-sv, sv);
    }
}

// Inverse-sign DFT-160 across a warp, stride-1 input mapping, packed f32x2.
// Input : lane L, v[j] = x[L + 32*j]; Output: o[r] = X[r + 5*brev5(L)]
__device__ __forceinline__ void fft160p(u64p v[5], u64p o[5], const Tw &tw, int lane){
    const float C1 =  0.30901699437494745f;
    const float C2 = -0.80901699437494734f;
    const float S1 =  0.95105651629515353f;
    const float S2 =  0.58778525229247314f;
    const u64p C1p  = pk2(C1, C1),  C2p = pk2(C2, C2);
    const u64p S1p  = pk2(S1, S1),  S2p = pk2(S2, S2);
    const u64p mS1p = pk2(-S1, -S1);
    const u64p NEG1 = pk2(-1.0f, -1.0f);
    const u64p PM   = pk2(-1.0f, 1.0f);
    const u64p MP   = pk2(1.0f, -1.0f);

    u64p s1 = add2p(v[1], v[4]);
    u64p d1 = fma2p(v[4], NEG1, v[1]);
    u64p s2 = add2p(v[2], v[3]);
    u64p d2 = fma2p(v[3], NEG1, v[2]);
    o[0] = add2p(v[0], add2p(s1, s2));
    u64p ua = fma2p(s2, C2p, fma2p(s1, C1p, v[0]));
    u64p ub = fma2p(s2, C1p, fma2p(s1, C2p, v[0]));
    u64p wa = fma2p(d2, S2p,  mul2p(d1, S1p));
    u64p wb = fma2p(d2, mS1p, mul2p(d1, S2p));
    u64p X1 = fma2p(swp2(wa), PM, ua);
    u64p X4 = fma2p(swp2(wa), MP, ua);
    u64p X2 = fma2p(swp2(wb), PM, ub);
    u64p X3 = fma2p(swp2(wb), MP, ub);
    o[1] = cmulp(X1, tw.tac[0], tw.tas[0]);
    o[2] = cmulp(X2, tw.tac[1], tw.tas[1]);
    o[3] = cmulp(X3, tw.tac[2], tw.tas[2]);
    o[4] = cmulp(X4, tw.tac[3], tw.tas[3]);

#pragma unroll
    for (int s = 0; s < 5; s++){
        int H = 16 >> s;
#pragma unroll
        for (int r = 0; r < 5; r++){
            float ox, oy; upk2(o[r], ox, oy);
            float px = __shfl_xor_sync(0xffffffffu, ox, H);
            float py = __shfl_xor_sync(0xffffffffu, oy, H);
            u64p T = fma2p(o[r], tw.g2[s], pk2(px, py));
            o[r] = cmulp(T, tw.stc[s], tw.sts[s]);
        }
    }
}

// Persistent pass 1: grid(SPEC_GRID) x 256. 1920 tiles (640 per tensor).
__global__ void __launch_bounds__(256)
pass1_kernel(const float* __restrict__ pur, const float* __restrict__ pui,
             const float* __restrict__ pvr, const float* __restrict__ pvi,
             const float* __restrict__ pwr, const float* __restrict__ pwi,
             const float* __restrict__ alpha_params)
{
    __shared__ char smbuf[48640];
    int wid  = threadIdx.x >> 5;
    int lane = threadIdx.x & 31;
    float scale = softplus_scale(alpha_params);

    Tw tw; make_tw(tw, lane);     // hoisted: once per block, reused for all tiles

#pragma unroll 1
    for (int tile = blockIdx.x; tile < 1920; tile += SPEC_GRID){
        int z  = tile / 640;
        int id = tile - z * 640;

        if (z < 2){
            // ---- t01 tile: one kd, 32 rows ----
            int kd = id / 5;
            int bx = id - kd * 5;
            const float* re = (z == 0) ? pur : pvr;
            const float* im = (z == 0) ? pui : pvi;
            int k = kd >> 3, d = kd & 7;

            __half2* sm1 = (__half2*)smbuf;   // [a_k]*33 + rowlocal(0..31)

#pragma unroll 1
            for (int r = 0; r < 4; r++){
                int rl = wid * 4 + r;
                int b  = bx * 32 + rl;
                int base = (z == 0) ? ((kd * GS + b) * GS)
                                    : (((k * GS + b) * 8 + d) * GS);
                u64p v[5], o[5];
#pragma unroll
                for (int j = 0; j < 5; j++){
                    int idx = base + lane + 32 * j;
                    v[j] = pk2(re[idx] * scale, im[idx] * scale);
                }
                fft160p(v, o, tw, lane);
#pragma unroll
                for (int r2 = 0; r2 < 5; r2++){
                    float x, y; upk2(o[r2], x, y);
                    sm1[(r2 + 5 * tw.k1) * 33 + rl] = __floats2half2_rn(x, y);
                }
            }
            __syncthreads();

#pragma unroll 1
            for (int idx = threadIdx.x; idx < GS * 8; idx += 256){
                int w = idx >> 3, g = idx & 7;
                const __half2* p = &sm1[w * 33 + g * 4];
                uint4 val;
                val.x = *(const unsigned*)&p[0];
                val.y = *(const unsigned*)&p[1];
                val.z = *(const unsigned*)&p[2];
                val.w = *(const unsigned*)&p[3];
                *(uint4*)&g_tmp_h[z][kd][w][bx * 32 + g * 4] = val;
            }
        } else {
            // ---- Pw tile: one k, 4 Y rows, all 8 d ----
            int k  = id / 40;
            int yb = id - k * 40;

            unsigned* smw  = (unsigned*)smbuf;                 // [y][X*9 + d] (pad 9)
            __half2*  sm1w = (__half2*)(smbuf + 4 * 1440 * 4); // [d][x_k*5 + y]

            {
                const float4* re4 = (const float4*)pwr;
                const float4* im4 = (const float4*)pwi;
                int y0 = yb * 4;
#pragma unroll 1
                for (int i = threadIdx.x; i < 1280; i += 256){
                    int X   = i >> 3;
                    int rem = i & 7;
                    int y   = rem >> 1;
                    int dg  = (rem & 1) * 4;
                    int gidx = ((k * GS + X) * GS + y0 + y) * 2 + (rem & 1);
                    float4 fr = re4[gidx];
                    float4 fi = im4[gidx];
                    unsigned* dst = &smw[y * 1440 + X * 9 + dg];
                    __half2 h0 = __floats2half2_rn(fr.x * scale, fi.x * scale);
                    __half2 h1 = __floats2half2_rn(fr.y * scale, fi.y * scale);
                    __half2 h2 = __floats2half2_rn(fr.z * scale, fi.z * scale);
                    __half2 h3 = __floats2half2_rn(fr.w * scale, fi.w * scale);
                    dst[0] = *(unsigned*)&h0;
                    dst[1] = *(unsigned*)&h1;
                    dst[2] = *(unsigned*)&h2;
                    dst[3] = *(unsigned*)&h3;
                }
            }
            __syncthreads();

#pragma unroll 1
            for (int yr = 0; yr < 4; yr++){
                u64p v[5], o[5];
#pragma unroll
                for (int j = 0; j < 5; j++){
                    unsigned u = smw[yr * 1440 + (lane + 32 * j) * 9 + wid];
                    float2 f = __half22float2(*(__half2*)&u);
                    v[j] = pk2(f.x, f.y);
                }
                fft160p(v, o, tw, lane);
#pragma unroll
                for (int r2 = 0; r2 < 5; r2++){
                    float x, y; upk2(o[r2], x, y);
                    sm1w[wid * 800 + (r2 + 5 * tw.k1) * 5 + yr] = __floats2half2_rn(x, y);
                }
            }
            __syncthreads();

#pragma unroll 1
            for (int i = threadIdx.x; i < 1280; i += 256){
                int d = i / 160;
                int x = i - d * 160;
                const __half2* p = &sm1w[d * 800 + x * 5];
                uint4 val;
                val.x = *(const unsigned*)&p[0];
                val.y = *(const unsigned*)&p[1];
                val.z = *(const unsigned*)&p[2];
                val.w = *(const unsigned*)&p[3];
                *(uint4*)&g_tmp_h[2][k * 8 + d][x][yb * 4] = val;
            }
        }
        __syncthreads();   // smbuf reuse barrier before next tile
    }
}

// Persistent pass 2: grid(SPEC_GRID) x 256. 960 tiles = 3 t x 16 kb x 20 wb.
__global__ void __launch_bounds__(256)
pass2_kernel()
{
    int wid  = threadIdx.x >> 5;
    int lane = threadIdx.x & 31;

    Tw tw; make_tw(tw, lane);

    __shared__ __half2 sm2[GS * 65];   // [h_k]*65 + ww*8 + wid

#pragma unroll 1
    for (int tile = blockIdx.x; tile < 960; tile += SPEC_GRID){
        int t  = tile / 320;
        int rr = tile - t * 320;
        int kb = rr / 20;
        int wb = rr - kb * 20;
        int kd = kb * 8 + wid;

#pragma unroll 1
        for (int ww = 0; ww < 8; ww++){
            const __half2* src = &g_tmp_h[t][kd][wb * 8 + ww][0];
            u64p v[5], o[5];
#pragma unroll
            for (int j = 0; j < 5; j++){
                float2 f = __half22float2(src[lane + 32 * j]);
                v[j] = pk2(f.x, f.y);
            }
            fft160p(v, o, tw, lane);
#pragma unroll
            for (int r2 = 0; r2 < 5; r2++){
                float x, y; upk2(o[r2], x, y);
                sm2[(r2 + 5 * tw.k1) * 65 + ww * 8 + wid] = __floats2half2_rn(x, y);
            }
        }
        __syncthreads();

#pragma unroll 1
        for (int idx = threadIdx.x; idx < GS * 16; idx += 256){
            int h = idx >> 4, rem = idx & 15, ww = rem >> 1, q = rem & 1;
            const __half2* p = &sm2[h * 65 + ww * 8 + q * 4];
            uint4 val;
            val.x = *(const unsigned*)&p[0];
            val.y = *(const unsigned*)&p[1];
            val.z = *(const unsigned*)&p[2];
            val.w = *(const unsigned*)&p[3];
            *(uint4*)&g_field_h[t][h][wb * 8 + ww][kb * 8 + q * 4] = val;
        }
        __syncthreads();   // sm2 reuse barrier
    }
}

// Sample: 16 lanes per point (2 points/warp), dense cell loads.
__global__ void __launch_bounds__(256)
sample_kernel(const float* __restrict__ xyz,
              const float* __restrict__ boundp,
              float* __restrict__ out, int npts)
{
    int warp_g = (int)((blockIdx.x * (unsigned)blockDim.x + threadIdx.x) >> 5);
    int lane = threadIdx.x & 31;
    int sub  = lane >> 4;
    int sl   = lane & 15;
    int gw   = warp_g * 2 + sub;
    if (gw >= npts) return;

    float invb = 1.0f / boundp[0];
    float p[3];
    p[0] = xyz[3*gw + 0] * invb;
    p[1] = xyz[3*gw + 1] * invb;
    p[2] = xyz[3*gw + 2] * invb;

    float wa0[3], wa1[3];
    int   c0i[3], c1i[3];
#pragma unroll
    for (int a = 0; a < 3; a++){
        float ia = (p[a] + 1.0f) * 0.5f * 159.0f;
        float fl = floorf(ia);
        float w  = ia - fl;
        int i0 = (int)fl, i1 = i0 + 1;
        float v0 = (i0 >= 0 && i0 <= 159) ? 1.0f : 0.0f;
        float v1 = (i1 >= 0 && i1 <= 159) ? 1.0f : 0.0f;
        c0i[a] = max(0, min(159, i0));
        c1i[a] = max(0, min(159, i1));
        wa0[a] = (1.0f - w) * v0;
        wa1[a] = w * v1;
    }

    const __half2* fld = &g_field_h[0][0][0][0];
    bool hi = (sl & 1) != 0;
    float gacc0 = 0.0f, gacc1 = 0.0f;

#pragma unroll
    for (int t = 0; t < 3; t++){
        const int ax = (t == 2) ? 0 : 2;
        const int ay = (t == 1) ? 0 : 1;

        __half2 w00h = __float2half2_rn(wa0[ax] * wa0[ay]);
        __half2 w01h = __float2half2_rn(wa1[ax] * wa0[ay]);
        __half2 w10h = __float2half2_rn(wa0[ax] * wa1[ay]);
        __half2 w11h = __float2half2_rn(wa1[ax] * wa1[ay]);

        int i0 = c0i[ax], i1 = c1i[ax];
        int j0 = c0i[ay], j1 = c1i[ay];

        const __half2* bp = fld + t * GS * GS * KD;
        const uint4* q00 = (const uint4*)(bp + (j0 * GS + i0) * KD) + sl;
        const uint4* q01 = (const uint4*)(bp + (j0 * GS + i1) * KD) + sl;
        const uint4* q10 = (const uint4*)(bp + (j1 * GS + i0) * KD) + sl;
        const uint4* q11 = (const uint4*)(bp + (j1 * GS + i1) * KD) + sl;

        float xt = (p[t] + 1.0f) * 0.5f;
        float s1, c1;
        sincospif(2.0f * xt, &s1, &c1);
        float cd[8], sd[8];
        cd[0] = 1.0f; sd[0] = 0.0f;
        float cc = c1, ss = s1;
        cd[1] = 2.0f * cc; sd[1] = 2.0f * ss;
#pragma unroll
        for (int j = 2; j < 8; j++){
            float nc = cc * cc - ss * ss;
            float ns = 2.0f * cc * ss;
            cc = nc; ss = ns;
            cd[j] = 2.0f * cc; sd[j] = 2.0f * ss;
        }
        float cs0 = hi ? cd[4] : cd[0], ss0 = hi ? sd[4] : sd[0];
        float cs1 = hi ? cd[5] : cd[1], ss1 = hi ? sd[5] : sd[1];
        float cs2 = hi ? cd[6] : cd[2], ss2 = hi ? sd[6] : sd[2];
        float cs3 = hi ? cd[7] : cd[3], ss3 = hi ? sd[7] : sd[3];

#pragma unroll
        for (int g = 0; g < 2; g++){
            uint4 u00 = q00[g * 16], u01 = q01[g * 16];
            uint4 u10 = q10[g * 16], u11 = q11[g * 16];
            float acc_s = 0.0f;
#pragma unroll
            for (int c = 0; c < 4; c++){
                __half2 acc = __hmul2(*(__half2*)&((&u00.x)[c]), w00h);
                acc = __hfma2(*(__half2*)&((&u01.x)[c]), w01h, acc);
                acc = __hfma2(*(__half2*)&((&u10.x)[c]), w10h, acc);
                acc = __hfma2(*(__half2*)&((&u11.x)[c]), w11h, acc);
                float2 f = __half22float2(acc);
                float csv = (c == 0) ? cs0 : (c == 1) ? cs1 : (c == 2) ? cs2 : cs3;
                float ssv = (c == 0) ? ss0 : (c == 1) ? ss1 : (c == 2) ? ss2 : ss3;
                acc_s += f.x * csv - f.y * ssv;
            }
            if (g == 0) gacc0 += acc_s; else gacc1 += acc_s;
        }
    }

    gacc0 += __shfl_xor_sync(0xffffffffu, gacc0, 1);
    gacc1 += __shfl_xor_sync(0xffffffffu, gacc1, 1);
    int  kout = hi ? (8 + (sl >> 1)) : (sl >> 1);
    float val = (hi ? gacc1 : gacc0) * INV_FSCALE;
    out[gw * NKS + kout] = val;
}

extern "C" void kernel_launch(void* const* d_in, const int* in_sizes, int n_in,
                              void* d_out, int out_size)
{
    const float* xyz   = (const float*)d_in[0];
    const float* bound = (const float*)d_in[1];
    const float* alpha = (const float*)d_in[2];
    const float* pur   = (const float*)d_in[3];
    const float* pui   = (const float*)d_in[4];
    const float* pvr   = (const float*)d_in[5];
    const float* pvi   = (const float*)d_in[6];
    const float* pwr   = (const float*)d_in[7];
    const float* pwi   = (const float*)d_in[8];

    pass1_kernel<<<SPEC_GRID, 256>>>(pur, pui, pvr, pvi, pwr, pwi, alpha);
    pass2_kernel<<<SPEC_GRID, 256>>>();

    int npts = in_sizes[0] / 3;
    int nwarps = (npts + 1) / 2;
    int nblocks = (nwarps * 32 + 255) / 256;
    sample_kernel<<<nblocks, 256>>>(xyz, bound, (float*)d_out, npts);
}